// round 7
// baseline (speedup 1.0000x reference)
#include <cuda_runtime.h>
#include <cuda_bf16.h>
#include <cstdint>

// ---------------- model constants ----------------
#define BB   32
#define SS   8
#define DD   768
#define NEE  8192
#define TT_  8192
#define HH   80
#define LL   2048
#define SCC  256
#define HOPS 3
#define KSPLIT 4

// ---------------- PTX helpers (sm_80-era: valid on base sm_103 target) ----------------
__device__ __forceinline__ uint32_t smem_to_u32(const void* smem_ptr) {
    uint32_t addr;
    asm("{ .reg .u64 tmp; cvta.to.shared.u64 tmp, %1; cvt.u32.u64 %0, tmp; }"
        : "=r"(addr) : "l"(smem_ptr));
    return addr;
}
#define CP_ASYNC16(dst_u32, src_ptr) \
    asm volatile("cp.async.cg.shared.global [%0], [%1], 16;" :: "r"(dst_u32), "l"(src_ptr))
#define CP_COMMIT() asm volatile("cp.async.commit_group;" ::: "memory")
#define CP_WAIT(n)  asm volatile("cp.async.wait_group %0;" :: "n"(n) : "memory")
#define LDMATRIX_X4(r0, r1, r2, r3, addr) \
    asm volatile("ldmatrix.sync.aligned.m8n8.x4.shared.b16 {%0,%1,%2,%3}, [%4];" \
        : "=r"(r0), "=r"(r1), "=r"(r2), "=r"(r3) : "r"(addr))
#define MMA_BF16(c, a0, a1, a2, a3, b0, b1) \
    asm volatile("mma.sync.aligned.m16n8k16.row.col.f32.bf16.bf16.f32 " \
        "{%0,%1,%2,%3}, {%4,%5,%6,%7}, {%8,%9}, {%0,%1,%2,%3};" \
        : "+f"((c)[0]), "+f"((c)[1]), "+f"((c)[2]), "+f"((c)[3]) \
        : "r"(a0), "r"(a1), "r"(a2), "r"(a3), "r"(b0), "r"(b1))
#define CVT_BF16X2_F32(result, a, b) \
    asm("cvt.rn.satfinite.bf16x2.f32 %0, %1, %2;" : "=r"(result) : "f"(b), "f"(a))

// ---------------- scratch (device globals; no allocation allowed) ----------------
__device__ float g_sum1[BB * SCC];
__device__ __nv_bfloat16 g_xb[BB * NEE];
__device__ float g_y[KSPLIT][TT_ * BB];
__device__ __nv_bfloat16 g_zb[BB * TT_];
__device__ float g_xp[HOPS][KSPLIT][BB * NEE];
__device__ float g_h[BB * 320];
__device__ float g_att[BB * 3];
__device__ __nv_bfloat16 g_Msb[(size_t)TT_ * NEE];
__device__ __nv_bfloat16 g_MoTb[(size_t)NEE * TT_];

// ---------------- EmbeddingBag + span dot, v2: warp-per-element, high MLP ----------------
// seg = searchsorted(offs, l, side='right') - 1, over SMEM-resident offsets
__device__ __forceinline__ int segsearch(const int* o, int l) {
    int lo = 0, hi = SCC;
    #pragma unroll
    for (int s = 0; s < 8; s++) {           // ceil(log2(256)) = 8 steps
        int mid = (lo + hi) >> 1;
        if (o[mid] <= l) lo = mid + 1; else hi = mid;
    }
    return lo - 1;
}

__global__ void __launch_bounds__(256) emb_dot_kernel(
        const float* __restrict__ emb,
        const int* __restrict__ ids,
        const float* __restrict__ att,
        const int* __restrict__ offs,
        const float* __restrict__ span_embs) {
    int b = blockIdx.x >> 4, chunk = blockIdx.x & 15;
    int tid = threadIdx.x, w = tid >> 5, lane = tid & 31;

    __shared__ float span_s[SS * DD];      // 24 KB
    __shared__ int   offs_s[SCC];
    __shared__ float sum1_s[SCC];

    const float4* sp  = (const float4*)(span_embs + (size_t)b * SS * DD);
    float4*       sps = (float4*)span_s;
    #pragma unroll
    for (int i = 0; i < (SS * DD / 4) / 256; i++) sps[tid + i * 256] = sp[tid + i * 256];
    offs_s[tid] = offs[b * SCC + tid];
    sum1_s[tid] = 0.f;
    __syncthreads();

    const int bL   = b * LL;
    const int base = chunk * 128 + w * 16;

    #pragma unroll
    for (int i = 0; i < 16; i += 2) {
        int la = base + i, lb = base + i + 1;
        int   ida = ids[bL + la], idb = ids[bL + lb];
        float wa  = att[bL + la], wb  = att[bL + lb];
        int sega = segsearch(offs_s, la);
        int segb = segsearch(offs_s, lb);
        const float4* ra = (const float4*)(emb + (size_t)ida * DD);
        const float4* rb = (const float4*)(emb + (size_t)idb * DD);
        const float4* sa = (const float4*)(span_s + (sega & 7) * DD);
        const float4* sb = (const float4*)(span_s + (segb & 7) * DD);
        float da = 0.f, db = 0.f;
        #pragma unroll
        for (int j = 0; j < 6; j++) {
            float4 va = ra[lane + 32 * j];
            float4 xa = sa[lane + 32 * j];
            da += va.x * xa.x + va.y * xa.y + va.z * xa.z + va.w * xa.w;
            float4 vb = rb[lane + 32 * j];
            float4 xb = sb[lane + 32 * j];
            db += vb.x * xb.x + vb.y * xb.y + vb.z * xb.z + vb.w * xb.w;
        }
        #pragma unroll
        for (int o = 16; o; o >>= 1) {
            da += __shfl_xor_sync(0xffffffffu, da, o);
            db += __shfl_xor_sync(0xffffffffu, db, o);
        }
        if (lane == 0) {
            atomicAdd(&sum1_s[sega], wa * da);
            atomicAdd(&sum1_s[segb], wb * db);
        }
    }
    __syncthreads();
    atomicAdd(&g_sum1[b * SCC + tid], sum1_s[tid]);
}

// ---------------- fused: softmax chain -> cand -> scatter -> NE softmax -> bf16 ----------------
__global__ void cand_softmax_kernel(const float* __restrict__ span_embs,
                                    const float* __restrict__ span_w,
                                    const float* __restrict__ span_b,
                                    const int* __restrict__ qid_inds) {
    int b = blockIdx.x, tid = threadIdx.x;
    __shared__ float ent[NEE];
    __shared__ float sh_sum1[256];
    __shared__ float sh_score[8];
    __shared__ float red[8];
    __shared__ float bc;

    #pragma unroll
    for (int i = 0; i < NEE / 256; i++) ent[tid + i * 256] = 0.f;

    int w = tid >> 5, lane = tid & 31;
    {
        const float* se = span_embs + ((size_t)b * SS + w) * DD;
        float d = 0.f;
        for (int i = lane; i < DD; i += 32) d += se[i] * span_w[i];
        #pragma unroll
        for (int o = 16; o; o >>= 1) d += __shfl_xor_sync(0xffffffffu, d, o);
        if (lane == 0) sh_score[w] = d + span_b[0];
    }
    sh_sum1[tid] = g_sum1[b * SCC + tid];
    __syncthreads();

    int c = tid & 31, s = tid >> 5;
    float m = -1e30f;
    #pragma unroll
    for (int s2 = 0; s2 < 8; s2++) m = fmaxf(m, sh_sum1[s2 * 32 + c]);
    float den = 0.f;
    #pragma unroll
    for (int s2 = 0; s2 < 8; s2++) den += expf(sh_sum1[s2 * 32 + c] - m);
    float sm1 = expf(sh_sum1[tid] - m) / den;
    float tv  = sh_score[s] * sm1;

    float bm = tv;
    #pragma unroll
    for (int o = 16; o; o >>= 1) bm = fmaxf(bm, __shfl_xor_sync(0xffffffffu, bm, o));
    if (lane == 0) red[w] = bm;
    __syncthreads();
    if (tid == 0) { float x = red[0]; for (int j = 1; j < 8; j++) x = fmaxf(x, red[j]); bc = x; }
    __syncthreads();
    bm = bc;
    float e = expf(tv - bm);
    float sm = e;
    #pragma unroll
    for (int o = 16; o; o >>= 1) sm += __shfl_xor_sync(0xffffffffu, sm, o);
    __syncthreads();
    if (lane == 0) red[w] = sm;
    __syncthreads();
    if (tid == 0) { float x = 0.f; for (int j = 0; j < 8; j++) x += red[j]; bc = x; }
    __syncthreads();
    float cand = e / bc;

    int qid = qid_inds[b * SCC + tid];
    if (qid < NEE) atomicAdd(&ent[qid], cand);
    __syncthreads();

    float v[NEE / 256];
    m = -1e30f;
    #pragma unroll
    for (int i = 0; i < NEE / 256; i++) { v[i] = ent[tid + i * 256]; m = fmaxf(m, v[i]); }
    #pragma unroll
    for (int o = 16; o; o >>= 1) m = fmaxf(m, __shfl_xor_sync(0xffffffffu, m, o));
    if (lane == 0) red[w] = m;
    __syncthreads();
    if (tid == 0) { float x = red[0]; for (int j = 1; j < 8; j++) x = fmaxf(x, red[j]); bc = x; }
    __syncthreads();
    m = bc;
    float ssum = 0.f;
    #pragma unroll
    for (int i = 0; i < NEE / 256; i++) { v[i] = expf(v[i] - m); ssum += v[i]; }
    #pragma unroll
    for (int o = 16; o; o >>= 1) ssum += __shfl_xor_sync(0xffffffffu, ssum, o);
    __syncthreads();
    if (lane == 0) red[w] = ssum;
    __syncthreads();
    if (tid == 0) { float x = 0.f; for (int j = 0; j < 8; j++) x += red[j]; bc = x; }
    __syncthreads();
    float inv = 1.f / bc;
    __nv_bfloat16* orow = g_xb + (size_t)b * NEE;
    #pragma unroll
    for (int i = 0; i < NEE / 256; i++) orow[tid + i * 256] = __float2bfloat16(v[i] * inv);
}

// ---------------- combine 4 split x partials -> bf16 g_xb ----------------
__global__ void combine_xb_kernel(const float* __restrict__ p0) {
    size_t i = (size_t)blockIdx.x * 256 + threadIdx.x;
    const size_t XS = (size_t)BB * NEE;
    float4 v = ((const float4*)p0)[i];
    #pragma unroll
    for (int k = 1; k < KSPLIT; k++) {
        float4 w2 = ((const float4*)(p0 + k * XS))[i];
        v.x += w2.x; v.y += w2.y; v.z += w2.z; v.w += w2.w;
    }
    uint2 o;
    CVT_BF16X2_F32(o.x, v.x, v.y);
    CVT_BF16X2_F32(o.y, v.z, v.w);
    ((uint2*)g_xb)[i] = o;
}

// ---------------- q = qn_emb @ red_w.T + red_b  (+ zero g_sum1) ----------------
__global__ void q_kernel(const float* __restrict__ qn,
                         const float* __restrict__ rw,
                         const float* __restrict__ rb) {
    int b = blockIdx.x;
    g_sum1[b * SCC + threadIdx.x] = 0.f;   // 256 threads == SCC
    int w = threadIdx.x >> 5, lane = threadIdx.x & 31;
    const float* q = qn + (size_t)b * DD;
    for (int h = w; h < HH; h += 8) {
        const float* r = rw + (size_t)h * DD;
        float d = 0.f;
        for (int i = lane; i < DD; i += 32) d += q[i] * r[i];
        #pragma unroll
        for (int o = 16; o; o >>= 1) d += __shfl_xor_sync(0xffffffffu, d, o);
        if (lane == 0) g_h[b * 320 + h] = d + rb[h];
    }
}

// ---------------- per-hop r = softmax(h@W.T+b), att logit ----------------
__global__ void r_kernel(const float* __restrict__ W, const float* __restrict__ bias,
                         const float* __restrict__ aw, const float* __restrict__ ab, int hop) {
    int b = blockIdx.x, tid = threadIdx.x;
    int Wd = HH * (hop + 1);
    __shared__ float sh_h[240];
    __shared__ float sh_v[80];
    for (int i = tid; i < Wd; i += 128) sh_h[i] = g_h[b * 320 + i];
    __syncthreads();
    if (tid < 80) {
        float a = bias[tid];
        const float* row = W + (size_t)tid * Wd;
        for (int i = 0; i < Wd; i++) a += sh_h[i] * row[i];
        sh_v[tid] = a;
    } else if (tid == 80) {
        float a = ab[0];
        for (int i = 0; i < Wd; i++) a += sh_h[i] * aw[i];
        g_att[b * 3 + hop] = a;
    }
    __syncthreads();
    float m = -1e30f;
    for (int i = 0; i < 80; i++) m = fmaxf(m, sh_v[i]);
    float s = 0.f;
    for (int i = 0; i < 80; i++) s += expf(sh_v[i] - m);
    if (tid < 80) g_h[b * 320 + Wd + tid] = expf(sh_v[tid] - m) / s;
}

// ---------------- Ms fp32 -> bf16 (same layout) ----------------
__global__ void convMs_kernel(const float* __restrict__ Ms) {
    size_t i = (size_t)blockIdx.x * 256 + threadIdx.x;
    float4 v0 = ((const float4*)Ms)[2 * i], v1 = ((const float4*)Ms)[2 * i + 1];
    uint4 o;
    CVT_BF16X2_F32(o.x, v0.x, v0.y);
    CVT_BF16X2_F32(o.y, v0.z, v0.w);
    CVT_BF16X2_F32(o.z, v1.x, v1.y);
    CVT_BF16X2_F32(o.w, v1.z, v1.w);
    ((uint4*)g_Msb)[i] = o;
}

// ---------------- transpose + convert Mo -> MoT bf16 [n][t] ----------------
__global__ void convT_kernel(const float* __restrict__ Mo) {
    __shared__ float sh[64][33];
    int t0 = blockIdx.x * 64, n0 = blockIdx.y * 32;
    int tx = threadIdx.x, ty = threadIdx.y;
    sh[ty][tx]      = Mo[(size_t)(t0 + ty) * NEE + n0 + tx];
    sh[ty + 32][tx] = Mo[(size_t)(t0 + ty + 32) * NEE + n0 + tx];
    __syncthreads();
    float lo = sh[2 * tx][ty], hi = sh[2 * tx + 1][ty];
    uint32_t pk; CVT_BF16X2_F32(pk, lo, hi);
    ((uint32_t*)g_MoTb)[(((size_t)(n0 + ty) * TT_ + t0) >> 1) + tx] = pk;
}

// =====================================================================
// HMMA GEMM (unchanged; measured 27.9us @ 62.9% DRAM)
// =====================================================================
#define KCHUNK 64
#define NIT    32
#define SA_STAGE 16384
#define SB_STAGE 4096
#define GEMM_SMEM (4 * (SA_STAGE + SB_STAGE))

template<bool TRANS_OUT>
__global__ void __launch_bounds__(256) hmma_gemm_kernel(
    const __nv_bfloat16* __restrict__ A,
    const __nv_bfloat16* __restrict__ Bb,
    float* __restrict__ OutBase, size_t out_split_stride) {

    extern __shared__ uint8_t smem[];
    const uint32_t sAb = smem_to_u32(smem);
    const uint32_t sBb = sAb + 4 * SA_STAGE;

    const int tid  = threadIdx.x;
    const int wid  = tid >> 5;
    const int lane = tid & 31;
    const int mbase  = blockIdx.x * 128;
    const int kstart = blockIdx.y * (KCHUNK * NIT);
    float* Out = OutBase + blockIdx.y * out_split_stride;

    const __nv_bfloat16* Ab = A + (size_t)mbase * 8192 + kstart;
    const __nv_bfloat16* Bx = Bb + kstart;

    const int arow = tid >> 3;
    const int ac   = tid & 7;
    auto prefetch = [&](int it) {
        const int stage = it & 3;
        const uint32_t sa = sAb + stage * SA_STAGE;
        const uint32_t sb = sBb + stage * SB_STAGE;
        const __nv_bfloat16* ga = Ab + it * KCHUNK;
        #pragma unroll
        for (int j = 0; j < 4; j++) {
            int row = arow + j * 32;
            uint32_t dst = sa + row * 128 + ((ac ^ (row & 7)) << 4);
            CP_ASYNC16(dst, ga + (size_t)row * 8192 + ac * 8);
        }
        uint32_t dstb = sb + arow * 128 + ((ac ^ (arow & 7)) << 4);
        CP_ASYNC16(dstb, Bx + (size_t)arow * 8192 + it * KCHUNK + ac * 8);
    };

    prefetch(0); CP_COMMIT();
    prefetch(1); CP_COMMIT();
    prefetch(2); CP_COMMIT();

    float acc[4][4];
    #pragma unroll
    for (int j = 0; j < 4; j++)
        #pragma unroll
        for (int i = 0; i < 4; i++) acc[j][i] = 0.f;

    const int a_quad = lane >> 3;
    const int a_rloc = wid * 16 + (lane & 7) + (a_quad & 1) * 8;
    const int a_cke  = a_quad >> 1;
    const int b_n    = ((lane >> 4) * 8) + (lane & 7);
    const int b_cke  = (lane >> 3) & 1;

    for (int it = 0; it < NIT; it++) {
        if (it + 2 < NIT) { CP_WAIT(2); }
        else if (it + 1 < NIT) { CP_WAIT(1); }
        else { CP_WAIT(0); }
        __syncthreads();
        if (it + 3 < NIT) { prefetch(it + 3); CP_COMMIT(); }

        const int stage = it & 3;
        const uint32_t sa = sAb + stage * SA_STAGE;
        const uint32_t sb = sBb + stage * SB_STAGE;

        #pragma unroll
        for (int s = 0; s < 4; s++) {
            uint32_t a0, a1, a2, a3;
            {
                int c = s * 2 + a_cke;
                uint32_t addr = sa + a_rloc * 128 + ((c ^ (a_rloc & 7)) << 4);
                LDMATRIX_X4(a0, a1, a2, a3, addr);
            }
            uint32_t bL[4], bH[4];
            {
                int c = s * 2 + b_cke;
                uint32_t addr0 = sb + b_n * 128 + ((c ^ (b_n & 7)) << 4);
                LDMATRIX_X4(bL[0], bL[1], bL[2], bL[3], addr0);
                int n1 = 16 + b_n;
                uint32_t addr1 = sb + n1 * 128 + ((c ^ (n1 & 7)) << 4);
                LDMATRIX_X4(bH[0], bH[1], bH[2], bH[3], addr1);
            }
            MMA_BF16(acc[0], a0, a1, a2, a3, bL[0], bL[1]);
            MMA_BF16(acc[1], a0, a1, a2, a3, bL[2], bL[3]);
            MMA_BF16(acc[2], a0, a1, a2, a3, bH[0], bH[1]);
            MMA_BF16(acc[3], a0, a1, a2, a3, bH[2], bH[3]);
        }
    }

    if (!TRANS_OUT) {
        const int row0 = mbase + wid * 16 + (lane >> 2);
        #pragma unroll
        for (int j = 0; j < 4; j++) {
            int col = j * 8 + (lane & 3) * 2;
            *(float2*)(Out + (size_t)row0 * 32 + col) = make_float2(acc[j][0], acc[j][1]);
            *(float2*)(Out + (size_t)(row0 + 8) * 32 + col) = make_float2(acc[j][2], acc[j][3]);
        }
    } else {
        float* ep = (float*)smem;
        __syncthreads();
        const int mloc = wid * 16 + (lane >> 2);
        #pragma unroll
        for (int j = 0; j < 4; j++) {
            int col = j * 8 + (lane & 3) * 2;
            ep[col * 128 + mloc]           = acc[j][0];
            ep[(col + 1) * 128 + mloc]     = acc[j][1];
            ep[col * 128 + mloc + 8]       = acc[j][2];
            ep[(col + 1) * 128 + mloc + 8] = acc[j][3];
        }
        __syncthreads();
        #pragma unroll
        for (int i = 0; i < 16; i++) {
            int idx = tid + i * 256;
            int cc = idx >> 7, mm = idx & 127;
            Out[(size_t)cc * 8192 + mbase + mm] = ep[idx];
        }
    }
}

// ---------------- z: zb[b][t] = bf16(sum_ks y[ks][t][b] * dot(Mp[t], r[b])) ----------------
__global__ void z_kernel(const float* __restrict__ Mp, int hop) {
    __shared__ float rsh[32][81];
    __shared__ float ztile[32][8];
    int tid = threadIdx.x;
    for (int i = tid; i < BB * HH; i += 256) {
        int bb = i / HH, h = i % HH;
        rsh[bb][h] = g_h[bb * 320 + HH * (hop + 1) + h];
    }
    __syncthreads();
    int w = tid >> 5, lane = tid & 31;
    int t = blockIdx.x * 8 + w;
    const float* mp = Mp + (size_t)t * HH;
    float p = 0.f;
    #pragma unroll
    for (int h = 0; h < HH; h++) p += mp[h] * rsh[lane][h];
    size_t off = (size_t)t * BB + lane;
    float ysum = 0.f;
    #pragma unroll
    for (int k = 0; k < KSPLIT; k++) ysum += g_y[k][off];
    ztile[lane][w] = ysum * p;
    __syncthreads();
    int b = tid >> 3, j = tid & 7;
    g_zb[(size_t)b * TT_ + blockIdx.x * 8 + j] = __float2bfloat16(ztile[b][j]);
}

// ---------------- final ----------------
__global__ void final_kernel(float* __restrict__ out) {
    int b = blockIdx.y;
    int n = blockIdx.x * 256 + threadIdx.x;
    float l0 = g_att[b * 3 + 0], l1 = g_att[b * 3 + 1], l2 = g_att[b * 3 + 2];
    float m = fmaxf(l0, fmaxf(l1, l2));
    float e0 = expf(l0 - m), e1 = expf(l1 - m), e2 = expf(l2 - m);
    float inv = 1.f / (e0 + e1 + e2);
    size_t off = (size_t)b * NEE + n;
    float x0 = 0.f, x1 = 0.f, x2 = 0.f;
    #pragma unroll
    for (int k = 0; k < KSPLIT; k++) {
        x0 += g_xp[0][k][off];
        x1 += g_xp[1][k][off];
        x2 += g_xp[2][k][off];
    }
    float v = x0 * e0 + x1 * e1 + x2 * e2;
    out[off] = 1.f / (1.f + expf(-v * inv));
}

// ---------------- launch ----------------
extern "C" void kernel_launch(void* const* d_in, const int* in_sizes, int n_in,
                              void* d_out, int out_size) {
    const float* span_embs = (const float*)d_in[0];
    const float* attention = (const float*)d_in[1];
    const float* qn_emb    = (const float*)d_in[2];
    const int*   trip_ids  = (const int*)  d_in[3];
    const int*   offsets   = (const int*)  d_in[4];
    const int*   qid_inds  = (const int*)  d_in[5];
    const float* emb_table = (const float*)d_in[6];
    const float* span_w    = (const float*)d_in[7];
    const float* span_b    = (const float*)d_in[8];
    const float* red_w     = (const float*)d_in[9];
    const float* red_b     = (const float*)d_in[10];
    const float* Ms        = (const float*)d_in[11];
    const float* Mo        = (const float*)d_in[12];
    const float* Mp        = (const float*)d_in[13];
    const float* inf_w[3]  = {(const float*)d_in[14], (const float*)d_in[16], (const float*)d_in[18]};
    const float* inf_b[3]  = {(const float*)d_in[15], (const float*)d_in[17], (const float*)d_in[19]};
    const float* att_w[3]  = {(const float*)d_in[20], (const float*)d_in[22], (const float*)d_in[24]};
    const float* att_b[3]  = {(const float*)d_in[21], (const float*)d_in[23], (const float*)d_in[25]};
    float* out = (float*)d_out;

    cudaFuncSetAttribute(hmma_gemm_kernel<false>,
                         cudaFuncAttributeMaxDynamicSharedMemorySize, GEMM_SMEM);
    cudaFuncSetAttribute(hmma_gemm_kernel<true>,
                         cudaFuncAttributeMaxDynamicSharedMemorySize, GEMM_SMEM);

    float *py, *pxp;
    cudaGetSymbolAddress((void**)&py,  g_y);
    cudaGetSymbolAddress((void**)&pxp, g_xp);
    __nv_bfloat16 *pMsb, *pMoT, *pxb, *pzb;
    cudaGetSymbolAddress((void**)&pMsb, g_Msb);
    cudaGetSymbolAddress((void**)&pMoT, g_MoTb);
    cudaGetSymbolAddress((void**)&pxb,  g_xb);
    cudaGetSymbolAddress((void**)&pzb,  g_zb);

    const size_t YS = (size_t)TT_ * BB;
    const size_t XS = (size_t)BB * NEE;

    // slot #4 = emb_dot v2 (the profiler captures launch #4); q (slot 3) zeroes g_sum1
    convMs_kernel<<<(int)(((size_t)TT_ * NEE / 8) / 256), 256>>>(Ms);
    convT_kernel<<<dim3(TT_ / 64, NEE / 32), dim3(32, 32)>>>(Mo);
    q_kernel<<<BB, 256>>>(qn_emb, red_w, red_b);
    emb_dot_kernel<<<BB * 16, 256>>>(emb_table, trip_ids, attention, offsets, span_embs);
    cand_softmax_kernel<<<BB, 256>>>(span_embs, span_w, span_b, qid_inds);
    hmma_gemm_kernel<false><<<dim3(64, KSPLIT), 256, GEMM_SMEM>>>(pMsb, pxb, py, YS);

    for (int hop = 0; hop < HOPS; hop++) {
        r_kernel<<<BB, 128>>>(inf_w[hop], inf_b[hop], att_w[hop], att_b[hop], hop);
        if (hop > 0) {
            combine_xb_kernel<<<256, 256>>>(pxp + (size_t)(hop - 1) * KSPLIT * XS);
            hmma_gemm_kernel<false><<<dim3(64, KSPLIT), 256, GEMM_SMEM>>>(pMsb, pxb, py, YS);
        }
        z_kernel<<<TT_ / 8, 256>>>(Mp, hop);
        hmma_gemm_kernel<true><<<dim3(64, KSPLIT), 256, GEMM_SMEM>>>(
            pMoT, pzb, pxp + (size_t)hop * KSPLIT * XS, XS);
    }
    final_kernel<<<dim3(NEE / 256, BB), 256>>>(out);
}

// round 8
// speedup vs baseline: 1.0006x; 1.0006x over previous
#include <cuda_runtime.h>
#include <cuda_bf16.h>
#include <cstdint>

// ---------------- model constants ----------------
#define BB   32
#define SS   8
#define DD   768
#define NEE  8192
#define TT_  8192
#define HH   80
#define LL   2048
#define SCC  256
#define HOPS 3
#define KSPLIT 4

// ---------------- PTX helpers (sm_80-era: valid on base sm_103 target) ----------------
__device__ __forceinline__ uint32_t smem_to_u32(const void* smem_ptr) {
    uint32_t addr;
    asm("{ .reg .u64 tmp; cvta.to.shared.u64 tmp, %1; cvt.u32.u64 %0, tmp; }"
        : "=r"(addr) : "l"(smem_ptr));
    return addr;
}
#define CP_ASYNC16(dst_u32, src_ptr) \
    asm volatile("cp.async.cg.shared.global [%0], [%1], 16;" :: "r"(dst_u32), "l"(src_ptr))
#define CP_COMMIT() asm volatile("cp.async.commit_group;" ::: "memory")
#define CP_WAIT(n)  asm volatile("cp.async.wait_group %0;" :: "n"(n) : "memory")
#define LDMATRIX_X4(r0, r1, r2, r3, addr) \
    asm volatile("ldmatrix.sync.aligned.m8n8.x4.shared.b16 {%0,%1,%2,%3}, [%4];" \
        : "=r"(r0), "=r"(r1), "=r"(r2), "=r"(r3) : "r"(addr))
#define MMA_BF16(c, a0, a1, a2, a3, b0, b1) \
    asm volatile("mma.sync.aligned.m16n8k16.row.col.f32.bf16.bf16.f32 " \
        "{%0,%1,%2,%3}, {%4,%5,%6,%7}, {%8,%9}, {%0,%1,%2,%3};" \
        : "+f"((c)[0]), "+f"((c)[1]), "+f"((c)[2]), "+f"((c)[3]) \
        : "r"(a0), "r"(a1), "r"(a2), "r"(a3), "r"(b0), "r"(b1))
#define CVT_BF16X2_F32(result, a, b) \
    asm("cvt.rn.satfinite.bf16x2.f32 %0, %1, %2;" : "=r"(result) : "f"(b), "f"(a))

// ---------------- scratch (device globals; no allocation allowed) ----------------
__device__ float g_sum1[BB * SCC];
__device__ __nv_bfloat16 g_xb[BB * NEE];
__device__ float g_y[KSPLIT][TT_ * BB];
__device__ __nv_bfloat16 g_zb[BB * TT_];
__device__ float g_xp[HOPS][KSPLIT][BB * NEE];
__device__ float g_h[BB * 320];
__device__ float g_att[BB * 3];
__device__ __nv_bfloat16 g_Msb[(size_t)TT_ * NEE];
__device__ __nv_bfloat16 g_MoTb[(size_t)NEE * TT_];

// ---------------- EmbeddingBag + span dot, v2: warp-per-element, high MLP ----------------
// seg = searchsorted(offs, l, side='right') - 1, over SMEM-resident offsets
__device__ __forceinline__ int segsearch(const int* o, int l) {
    int lo = 0, hi = SCC;
    #pragma unroll
    for (int s = 0; s < 8; s++) {           // ceil(log2(256)) = 8 steps
        int mid = (lo + hi) >> 1;
        if (o[mid] <= l) lo = mid + 1; else hi = mid;
    }
    return lo - 1;
}

__global__ void __launch_bounds__(256) emb_dot_kernel(
        const float* __restrict__ emb,
        const int* __restrict__ ids,
        const float* __restrict__ att,
        const int* __restrict__ offs,
        const float* __restrict__ span_embs) {
    int b = blockIdx.x >> 4, chunk = blockIdx.x & 15;
    int tid = threadIdx.x, w = tid >> 5, lane = tid & 31;

    __shared__ float span_s[SS * DD];      // 24 KB
    __shared__ int   offs_s[SCC];
    __shared__ float sum1_s[SCC];

    const float4* sp  = (const float4*)(span_embs + (size_t)b * SS * DD);
    float4*       sps = (float4*)span_s;
    #pragma unroll
    for (int i = 0; i < (SS * DD / 4) / 256; i++) sps[tid + i * 256] = sp[tid + i * 256];
    offs_s[tid] = offs[b * SCC + tid];
    sum1_s[tid] = 0.f;
    __syncthreads();

    const int bL   = b * LL;
    const int base = chunk * 128 + w * 16;

    #pragma unroll
    for (int i = 0; i < 16; i += 2) {
        int la = base + i, lb = base + i + 1;
        int   ida = ids[bL + la], idb = ids[bL + lb];
        float wa  = att[bL + la], wb  = att[bL + lb];
        int sega = segsearch(offs_s, la);
        int segb = segsearch(offs_s, lb);
        const float4* ra = (const float4*)(emb + (size_t)ida * DD);
        const float4* rb = (const float4*)(emb + (size_t)idb * DD);
        const float4* sa = (const float4*)(span_s + (sega & 7) * DD);
        const float4* sb = (const float4*)(span_s + (segb & 7) * DD);
        float da = 0.f, db = 0.f;
        #pragma unroll
        for (int j = 0; j < 6; j++) {
            float4 va = ra[lane + 32 * j];
            float4 xa = sa[lane + 32 * j];
            da += va.x * xa.x + va.y * xa.y + va.z * xa.z + va.w * xa.w;
            float4 vb = rb[lane + 32 * j];
            float4 xb = sb[lane + 32 * j];
            db += vb.x * xb.x + vb.y * xb.y + vb.z * xb.z + vb.w * xb.w;
        }
        #pragma unroll
        for (int o = 16; o; o >>= 1) {
            da += __shfl_xor_sync(0xffffffffu, da, o);
            db += __shfl_xor_sync(0xffffffffu, db, o);
        }
        if (lane == 0) {
            atomicAdd(&sum1_s[sega], wa * da);
            atomicAdd(&sum1_s[segb], wb * db);
        }
    }
    __syncthreads();
    atomicAdd(&g_sum1[b * SCC + tid], sum1_s[tid]);
}

// ---------------- fused: softmax chain -> cand -> scatter -> NE softmax -> bf16 ----------------
__global__ void cand_softmax_kernel(const float* __restrict__ span_embs,
                                    const float* __restrict__ span_w,
                                    const float* __restrict__ span_b,
                                    const int* __restrict__ qid_inds) {
    int b = blockIdx.x, tid = threadIdx.x;
    __shared__ float ent[NEE];
    __shared__ float sh_sum1[256];
    __shared__ float sh_score[8];
    __shared__ float red[8];
    __shared__ float bc;

    #pragma unroll
    for (int i = 0; i < NEE / 256; i++) ent[tid + i * 256] = 0.f;

    int w = tid >> 5, lane = tid & 31;
    {
        const float* se = span_embs + ((size_t)b * SS + w) * DD;
        float d = 0.f;
        for (int i = lane; i < DD; i += 32) d += se[i] * span_w[i];
        #pragma unroll
        for (int o = 16; o; o >>= 1) d += __shfl_xor_sync(0xffffffffu, d, o);
        if (lane == 0) sh_score[w] = d + span_b[0];
    }
    sh_sum1[tid] = g_sum1[b * SCC + tid];
    __syncthreads();

    int c = tid & 31, s = tid >> 5;
    float m = -1e30f;
    #pragma unroll
    for (int s2 = 0; s2 < 8; s2++) m = fmaxf(m, sh_sum1[s2 * 32 + c]);
    float den = 0.f;
    #pragma unroll
    for (int s2 = 0; s2 < 8; s2++) den += expf(sh_sum1[s2 * 32 + c] - m);
    float sm1 = expf(sh_sum1[tid] - m) / den;
    float tv  = sh_score[s] * sm1;

    float bm = tv;
    #pragma unroll
    for (int o = 16; o; o >>= 1) bm = fmaxf(bm, __shfl_xor_sync(0xffffffffu, bm, o));
    if (lane == 0) red[w] = bm;
    __syncthreads();
    if (tid == 0) { float x = red[0]; for (int j = 1; j < 8; j++) x = fmaxf(x, red[j]); bc = x; }
    __syncthreads();
    bm = bc;
    float e = expf(tv - bm);
    float sm = e;
    #pragma unroll
    for (int o = 16; o; o >>= 1) sm += __shfl_xor_sync(0xffffffffu, sm, o);
    __syncthreads();
    if (lane == 0) red[w] = sm;
    __syncthreads();
    if (tid == 0) { float x = 0.f; for (int j = 0; j < 8; j++) x += red[j]; bc = x; }
    __syncthreads();
    float cand = e / bc;

    int qid = qid_inds[b * SCC + tid];
    if (qid < NEE) atomicAdd(&ent[qid], cand);
    __syncthreads();

    float v[NEE / 256];
    m = -1e30f;
    #pragma unroll
    for (int i = 0; i < NEE / 256; i++) { v[i] = ent[tid + i * 256]; m = fmaxf(m, v[i]); }
    #pragma unroll
    for (int o = 16; o; o >>= 1) m = fmaxf(m, __shfl_xor_sync(0xffffffffu, m, o));
    if (lane == 0) red[w] = m;
    __syncthreads();
    if (tid == 0) { float x = red[0]; for (int j = 1; j < 8; j++) x = fmaxf(x, red[j]); bc = x; }
    __syncthreads();
    m = bc;
    float ssum = 0.f;
    #pragma unroll
    for (int i = 0; i < NEE / 256; i++) { v[i] = expf(v[i] - m); ssum += v[i]; }
    #pragma unroll
    for (int o = 16; o; o >>= 1) ssum += __shfl_xor_sync(0xffffffffu, ssum, o);
    __syncthreads();
    if (lane == 0) red[w] = ssum;
    __syncthreads();
    if (tid == 0) { float x = 0.f; for (int j = 0; j < 8; j++) x += red[j]; bc = x; }
    __syncthreads();
    float inv = 1.f / bc;
    __nv_bfloat16* orow = g_xb + (size_t)b * NEE;
    #pragma unroll
    for (int i = 0; i < NEE / 256; i++) orow[tid + i * 256] = __float2bfloat16(v[i] * inv);
}

// ---------------- combine 4 split x partials -> bf16 g_xb ----------------
__global__ void combine_xb_kernel(const float* __restrict__ p0) {
    size_t i = (size_t)blockIdx.x * 256 + threadIdx.x;
    const size_t XS = (size_t)BB * NEE;
    float4 v = ((const float4*)p0)[i];
    #pragma unroll
    for (int k = 1; k < KSPLIT; k++) {
        float4 w2 = ((const float4*)(p0 + k * XS))[i];
        v.x += w2.x; v.y += w2.y; v.z += w2.z; v.w += w2.w;
    }
    uint2 o;
    CVT_BF16X2_F32(o.x, v.x, v.y);
    CVT_BF16X2_F32(o.y, v.z, v.w);
    ((uint2*)g_xb)[i] = o;
}

// ---------------- q = qn_emb @ red_w.T + red_b  (+ zero g_sum1) ----------------
__global__ void q_kernel(const float* __restrict__ qn,
                         const float* __restrict__ rw,
                         const float* __restrict__ rb) {
    int b = blockIdx.x;
    g_sum1[b * SCC + threadIdx.x] = 0.f;   // 256 threads == SCC
    int w = threadIdx.x >> 5, lane = threadIdx.x & 31;
    const float* q = qn + (size_t)b * DD;
    for (int h = w; h < HH; h += 8) {
        const float* r = rw + (size_t)h * DD;
        float d = 0.f;
        for (int i = lane; i < DD; i += 32) d += q[i] * r[i];
        #pragma unroll
        for (int o = 16; o; o >>= 1) d += __shfl_xor_sync(0xffffffffu, d, o);
        if (lane == 0) g_h[b * 320 + h] = d + rb[h];
    }
}

// ---------------- per-hop r = softmax(h@W.T+b), att logit ----------------
__global__ void r_kernel(const float* __restrict__ W, const float* __restrict__ bias,
                         const float* __restrict__ aw, const float* __restrict__ ab, int hop) {
    int b = blockIdx.x, tid = threadIdx.x;
    int Wd = HH * (hop + 1);
    __shared__ float sh_h[240];
    __shared__ float sh_v[80];
    for (int i = tid; i < Wd; i += 128) sh_h[i] = g_h[b * 320 + i];
    __syncthreads();
    if (tid < 80) {
        float a = bias[tid];
        const float* row = W + (size_t)tid * Wd;
        for (int i = 0; i < Wd; i++) a += sh_h[i] * row[i];
        sh_v[tid] = a;
    } else if (tid == 80) {
        float a = ab[0];
        for (int i = 0; i < Wd; i++) a += sh_h[i] * aw[i];
        g_att[b * 3 + hop] = a;
    }
    __syncthreads();
    float m = -1e30f;
    for (int i = 0; i < 80; i++) m = fmaxf(m, sh_v[i]);
    float s = 0.f;
    for (int i = 0; i < 80; i++) s += expf(sh_v[i] - m);
    if (tid < 80) g_h[b * 320 + Wd + tid] = expf(sh_v[tid] - m) / s;
}

// ---------------- Ms fp32 -> bf16 (same layout) ----------------
__global__ void convMs_kernel(const float* __restrict__ Ms) {
    size_t i = (size_t)blockIdx.x * 256 + threadIdx.x;
    float4 v0 = ((const float4*)Ms)[2 * i], v1 = ((const float4*)Ms)[2 * i + 1];
    uint4 o;
    CVT_BF16X2_F32(o.x, v0.x, v0.y);
    CVT_BF16X2_F32(o.y, v0.z, v0.w);
    CVT_BF16X2_F32(o.z, v1.x, v1.y);
    CVT_BF16X2_F32(o.w, v1.z, v1.w);
    ((uint4*)g_Msb)[i] = o;
}

// ---------------- transpose + convert Mo -> MoT bf16 [n][t] ----------------
__global__ void convT_kernel(const float* __restrict__ Mo) {
    __shared__ float sh[64][33];
    int t0 = blockIdx.x * 64, n0 = blockIdx.y * 32;
    int tx = threadIdx.x, ty = threadIdx.y;
    sh[ty][tx]      = Mo[(size_t)(t0 + ty) * NEE + n0 + tx];
    sh[ty + 32][tx] = Mo[(size_t)(t0 + ty + 32) * NEE + n0 + tx];
    __syncthreads();
    float lo = sh[2 * tx][ty], hi = sh[2 * tx + 1][ty];
    uint32_t pk; CVT_BF16X2_F32(pk, lo, hi);
    ((uint32_t*)g_MoTb)[(((size_t)(n0 + ty) * TT_ + t0) >> 1) + tx] = pk;
}

// =====================================================================
// HMMA GEMM (unchanged; measured 27.9us @ 62.9% DRAM)
// =====================================================================
#define KCHUNK 64
#define NIT    32
#define SA_STAGE 16384
#define SB_STAGE 4096
#define GEMM_SMEM (4 * (SA_STAGE + SB_STAGE))

template<bool TRANS_OUT>
__global__ void __launch_bounds__(256) hmma_gemm_kernel(
    const __nv_bfloat16* __restrict__ A,
    const __nv_bfloat16* __restrict__ Bb,
    float* __restrict__ OutBase, size_t out_split_stride) {

    extern __shared__ uint8_t smem[];
    const uint32_t sAb = smem_to_u32(smem);
    const uint32_t sBb = sAb + 4 * SA_STAGE;

    const int tid  = threadIdx.x;
    const int wid  = tid >> 5;
    const int lane = tid & 31;
    const int mbase  = blockIdx.x * 128;
    const int kstart = blockIdx.y * (KCHUNK * NIT);
    float* Out = OutBase + blockIdx.y * out_split_stride;

    const __nv_bfloat16* Ab = A + (size_t)mbase * 8192 + kstart;
    const __nv_bfloat16* Bx = Bb + kstart;

    const int arow = tid >> 3;
    const int ac   = tid & 7;
    auto prefetch = [&](int it) {
        const int stage = it & 3;
        const uint32_t sa = sAb + stage * SA_STAGE;
        const uint32_t sb = sBb + stage * SB_STAGE;
        const __nv_bfloat16* ga = Ab + it * KCHUNK;
        #pragma unroll
        for (int j = 0; j < 4; j++) {
            int row = arow + j * 32;
            uint32_t dst = sa + row * 128 + ((ac ^ (row & 7)) << 4);
            CP_ASYNC16(dst, ga + (size_t)row * 8192 + ac * 8);
        }
        uint32_t dstb = sb + arow * 128 + ((ac ^ (arow & 7)) << 4);
        CP_ASYNC16(dstb, Bx + (size_t)arow * 8192 + it * KCHUNK + ac * 8);
    };

    prefetch(0); CP_COMMIT();
    prefetch(1); CP_COMMIT();
    prefetch(2); CP_COMMIT();

    float acc[4][4];
    #pragma unroll
    for (int j = 0; j < 4; j++)
        #pragma unroll
        for (int i = 0; i < 4; i++) acc[j][i] = 0.f;

    const int a_quad = lane >> 3;
    const int a_rloc = wid * 16 + (lane & 7) + (a_quad & 1) * 8;
    const int a_cke  = a_quad >> 1;
    const int b_n    = ((lane >> 4) * 8) + (lane & 7);
    const int b_cke  = (lane >> 3) & 1;

    for (int it = 0; it < NIT; it++) {
        if (it + 2 < NIT) { CP_WAIT(2); }
        else if (it + 1 < NIT) { CP_WAIT(1); }
        else { CP_WAIT(0); }
        __syncthreads();
        if (it + 3 < NIT) { prefetch(it + 3); CP_COMMIT(); }

        const int stage = it & 3;
        const uint32_t sa = sAb + stage * SA_STAGE;
        const uint32_t sb = sBb + stage * SB_STAGE;

        #pragma unroll
        for (int s = 0; s < 4; s++) {
            uint32_t a0, a1, a2, a3;
            {
                int c = s * 2 + a_cke;
                uint32_t addr = sa + a_rloc * 128 + ((c ^ (a_rloc & 7)) << 4);
                LDMATRIX_X4(a0, a1, a2, a3, addr);
            }
            uint32_t bL[4], bH[4];
            {
                int c = s * 2 + b_cke;
                uint32_t addr0 = sb + b_n * 128 + ((c ^ (b_n & 7)) << 4);
                LDMATRIX_X4(bL[0], bL[1], bL[2], bL[3], addr0);
                int n1 = 16 + b_n;
                uint32_t addr1 = sb + n1 * 128 + ((c ^ (n1 & 7)) << 4);
                LDMATRIX_X4(bH[0], bH[1], bH[2], bH[3], addr1);
            }
            MMA_BF16(acc[0], a0, a1, a2, a3, bL[0], bL[1]);
            MMA_BF16(acc[1], a0, a1, a2, a3, bL[2], bL[3]);
            MMA_BF16(acc[2], a0, a1, a2, a3, bH[0], bH[1]);
            MMA_BF16(acc[3], a0, a1, a2, a3, bH[2], bH[3]);
        }
    }

    if (!TRANS_OUT) {
        const int row0 = mbase + wid * 16 + (lane >> 2);
        #pragma unroll
        for (int j = 0; j < 4; j++) {
            int col = j * 8 + (lane & 3) * 2;
            *(float2*)(Out + (size_t)row0 * 32 + col) = make_float2(acc[j][0], acc[j][1]);
            *(float2*)(Out + (size_t)(row0 + 8) * 32 + col) = make_float2(acc[j][2], acc[j][3]);
        }
    } else {
        float* ep = (float*)smem;
        __syncthreads();
        const int mloc = wid * 16 + (lane >> 2);
        #pragma unroll
        for (int j = 0; j < 4; j++) {
            int col = j * 8 + (lane & 3) * 2;
            ep[col * 128 + mloc]           = acc[j][0];
            ep[(col + 1) * 128 + mloc]     = acc[j][1];
            ep[col * 128 + mloc + 8]       = acc[j][2];
            ep[(col + 1) * 128 + mloc + 8] = acc[j][3];
        }
        __syncthreads();
        #pragma unroll
        for (int i = 0; i < 16; i++) {
            int idx = tid + i * 256;
            int cc = idx >> 7, mm = idx & 127;
            Out[(size_t)cc * 8192 + mbase + mm] = ep[idx];
        }
    }
}

// ---------------- z: zb[b][t] = bf16(sum_ks y[ks][t][b] * dot(Mp[t], r[b])) ----------------
__global__ void z_kernel(const float* __restrict__ Mp, int hop) {
    __shared__ float rsh[32][81];
    __shared__ float ztile[32][8];
    int tid = threadIdx.x;
    for (int i = tid; i < BB * HH; i += 256) {
        int bb = i / HH, h = i % HH;
        rsh[bb][h] = g_h[bb * 320 + HH * (hop + 1) + h];
    }
    __syncthreads();
    int w = tid >> 5, lane = tid & 31;
    int t = blockIdx.x * 8 + w;
    const float* mp = Mp + (size_t)t * HH;
    float p = 0.f;
    #pragma unroll
    for (int h = 0; h < HH; h++) p += mp[h] * rsh[lane][h];
    size_t off = (size_t)t * BB + lane;
    float ysum = 0.f;
    #pragma unroll
    for (int k = 0; k < KSPLIT; k++) ysum += g_y[k][off];
    ztile[lane][w] = ysum * p;
    __syncthreads();
    int b = tid >> 3, j = tid & 7;
    g_zb[(size_t)b * TT_ + blockIdx.x * 8 + j] = __float2bfloat16(ztile[b][j]);
}

// ---------------- final ----------------
__global__ void final_kernel(float* __restrict__ out) {
    int b = blockIdx.y;
    int n = blockIdx.x * 256 + threadIdx.x;
    float l0 = g_att[b * 3 + 0], l1 = g_att[b * 3 + 1], l2 = g_att[b * 3 + 2];
    float m = fmaxf(l0, fmaxf(l1, l2));
    float e0 = expf(l0 - m), e1 = expf(l1 - m), e2 = expf(l2 - m);
    float inv = 1.f / (e0 + e1 + e2);
    size_t off = (size_t)b * NEE + n;
    float x0 = 0.f, x1 = 0.f, x2 = 0.f;
    #pragma unroll
    for (int k = 0; k < KSPLIT; k++) {
        x0 += g_xp[0][k][off];
        x1 += g_xp[1][k][off];
        x2 += g_xp[2][k][off];
    }
    float v = x0 * e0 + x1 * e1 + x2 * e2;
    out[off] = 1.f / (1.f + expf(-v * inv));
}

// ---------------- launch ----------------
extern "C" void kernel_launch(void* const* d_in, const int* in_sizes, int n_in,
                              void* d_out, int out_size) {
    const float* span_embs = (const float*)d_in[0];
    const float* attention = (const float*)d_in[1];
    const float* qn_emb    = (const float*)d_in[2];
    const int*   trip_ids  = (const int*)  d_in[3];
    const int*   offsets   = (const int*)  d_in[4];
    const int*   qid_inds  = (const int*)  d_in[5];
    const float* emb_table = (const float*)d_in[6];
    const float* span_w    = (const float*)d_in[7];
    const float* span_b    = (const float*)d_in[8];
    const float* red_w     = (const float*)d_in[9];
    const float* red_b     = (const float*)d_in[10];
    const float* Ms        = (const float*)d_in[11];
    const float* Mo        = (const float*)d_in[12];
    const float* Mp        = (const float*)d_in[13];
    const float* inf_w[3]  = {(const float*)d_in[14], (const float*)d_in[16], (const float*)d_in[18]};
    const float* inf_b[3]  = {(const float*)d_in[15], (const float*)d_in[17], (const float*)d_in[19]};
    const float* att_w[3]  = {(const float*)d_in[20], (const float*)d_in[22], (const float*)d_in[24]};
    const float* att_b[3]  = {(const float*)d_in[21], (const float*)d_in[23], (const float*)d_in[25]};
    float* out = (float*)d_out;

    cudaFuncSetAttribute(hmma_gemm_kernel<false>,
                         cudaFuncAttributeMaxDynamicSharedMemorySize, GEMM_SMEM);
    cudaFuncSetAttribute(hmma_gemm_kernel<true>,
                         cudaFuncAttributeMaxDynamicSharedMemorySize, GEMM_SMEM);

    float *py, *pxp;
    cudaGetSymbolAddress((void**)&py,  g_y);
    cudaGetSymbolAddress((void**)&pxp, g_xp);
    __nv_bfloat16 *pMsb, *pMoT, *pxb, *pzb;
    cudaGetSymbolAddress((void**)&pMsb, g_Msb);
    cudaGetSymbolAddress((void**)&pMoT, g_MoTb);
    cudaGetSymbolAddress((void**)&pxb,  g_xb);
    cudaGetSymbolAddress((void**)&pzb,  g_zb);

    const size_t YS = (size_t)TT_ * BB;
    const size_t XS = (size_t)BB * NEE;

    // slot #4 = emb_dot v2 (the profiler captures launch #4); q (slot 3) zeroes g_sum1
    convMs_kernel<<<(int)(((size_t)TT_ * NEE / 8) / 256), 256>>>(Ms);
    convT_kernel<<<dim3(TT_ / 64, NEE / 32), dim3(32, 32)>>>(Mo);
    q_kernel<<<BB, 256>>>(qn_emb, red_w, red_b);
    emb_dot_kernel<<<BB * 16, 256>>>(emb_table, trip_ids, attention, offsets, span_embs);
    cand_softmax_kernel<<<BB, 256>>>(span_embs, span_w, span_b, qid_inds);
    hmma_gemm_kernel<false><<<dim3(64, KSPLIT), 256, GEMM_SMEM>>>(pMsb, pxb, py, YS);

    for (int hop = 0; hop < HOPS; hop++) {
        r_kernel<<<BB, 128>>>(inf_w[hop], inf_b[hop], att_w[hop], att_b[hop], hop);
        if (hop > 0) {
            combine_xb_kernel<<<256, 256>>>(pxp + (size_t)(hop - 1) * KSPLIT * XS);
            hmma_gemm_kernel<false><<<dim3(64, KSPLIT), 256, GEMM_SMEM>>>(pMsb, pxb, py, YS);
        }
        z_kernel<<<TT_ / 8, 256>>>(Mp, hop);
        hmma_gemm_kernel<true><<<dim3(64, KSPLIT), 256, GEMM_SMEM>>>(
            pMoT, pzb, pxp + (size_t)hop * KSPLIT * XS, XS);
    }
    final_kernel<<<dim3(NEE / 256, BB), 256>>>(out);
}

// round 9
// speedup vs baseline: 1.1319x; 1.1312x over previous
#include <cuda_runtime.h>
#include <cuda_bf16.h>
#include <cstdint>

// ---------------- model constants ----------------
#define BB   32
#define SS   8
#define DD   768
#define NEE  8192
#define TT_  8192
#define HH   80
#define LL   2048
#define SCC  256
#define HOPS 3
#define KSPLIT 4

// ---------------- PTX helpers ----------------
__device__ __forceinline__ uint32_t smem_to_u32(const void* smem_ptr) {
    uint32_t addr;
    asm("{ .reg .u64 tmp; cvta.to.shared.u64 tmp, %1; cvt.u32.u64 %0, tmp; }"
        : "=r"(addr) : "l"(smem_ptr));
    return addr;
}
#define CP_ASYNC16(dst_u32, src_ptr) \
    asm volatile("cp.async.cg.shared.global [%0], [%1], 16;" :: "r"(dst_u32), "l"(src_ptr))
#define CP_COMMIT() asm volatile("cp.async.commit_group;" ::: "memory")
#define CP_WAIT(n)  asm volatile("cp.async.wait_group %0;" :: "n"(n) : "memory")
#define LDMATRIX_X4(r0, r1, r2, r3, addr) \
    asm volatile("ldmatrix.sync.aligned.m8n8.x4.shared.b16 {%0,%1,%2,%3}, [%4];" \
        : "=r"(r0), "=r"(r1), "=r"(r2), "=r"(r3) : "r"(addr))
// fp8 MMA: A=e4m3 (matrix), B=e5m2 (activation), fp32 accum
#define MMA_FP8(c, a0, a1, a2, a3, b0, b1) \
    asm volatile("mma.sync.aligned.m16n8k32.row.col.f32.e4m3.e5m2.f32 " \
        "{%0,%1,%2,%3}, {%4,%5,%6,%7}, {%8,%9}, {%0,%1,%2,%3};" \
        : "+f"((c)[0]), "+f"((c)[1]), "+f"((c)[2]), "+f"((c)[3]) \
        : "r"(a0), "r"(a1), "r"(a2), "r"(a3), "r"(b0), "r"(b1))
#define CVT_E4M3X2(r, hi, lo) \
    asm("cvt.rn.satfinite.e4m3x2.f32 %0, %1, %2;" : "=h"(r) : "f"(hi), "f"(lo))
#define CVT_E5M2X2(r, hi, lo) \
    asm("cvt.rn.satfinite.e5m2x2.f32 %0, %1, %2;" : "=h"(r) : "f"(hi), "f"(lo))

// ---------------- scaling constants (power-of-2, tracked symbolically) ----------------
// SM = 128 (matrices).  SX[hop] for x fed to GEMM1; SZ[hop] for z fed to GEMM2.
// CZ[hop]  = SZ[hop] / (SM*SX[hop])        (applied in z_kernel)
// CB[hop]  = SX[hop] / (SM*SZ[hop-1])      (applied in combine_xb, hop>=1)
// FX[hop]  = 1 / (SM*SZ[hop])              (applied in final)
#define SCALE_M 128.0f

// ---------------- scratch (device globals) ----------------
__device__ float g_sum1[BB * SCC];
__device__ __align__(16) uint8_t g_xb[BB * NEE];          // x, e5m2 scaled
__device__ float g_y[KSPLIT][TT_ * BB];                   // y k-split partials (fp32, scaled)
__device__ __align__(16) uint8_t g_zb[BB * TT_];          // z, e5m2 scaled
__device__ float g_xp[HOPS][KSPLIT][BB * NEE];            // x partials (fp32, scaled)
__device__ float g_h[BB * 320];
__device__ float g_att[BB * 3];
__device__ __align__(16) uint8_t g_Msb[(size_t)TT_ * NEE];  // Ms e4m3 x128, row-major [t][n]
__device__ __align__(16) uint8_t g_MoTb[(size_t)NEE * TT_]; // Mo^T e4m3 x128, [n][t]

// ---------------- Ms fp32 -> e4m3 x128 (+ zero g_sum1 in blocks 0..31) ----------------
__global__ void convMs_kernel(const float* __restrict__ Ms) {
    if (blockIdx.x < 32) g_sum1[blockIdx.x * 256 + threadIdx.x] = 0.f;
    size_t i = (size_t)blockIdx.x * 256 + threadIdx.x;   // 8 elements each
    float4 v0 = ((const float4*)Ms)[2 * i], v1 = ((const float4*)Ms)[2 * i + 1];
    uint16_t u0, u1, u2, u3;
    CVT_E4M3X2(u0, v0.y * SCALE_M, v0.x * SCALE_M);
    CVT_E4M3X2(u1, v0.w * SCALE_M, v0.z * SCALE_M);
    CVT_E4M3X2(u2, v1.y * SCALE_M, v1.x * SCALE_M);
    CVT_E4M3X2(u3, v1.w * SCALE_M, v1.z * SCALE_M);
    uint2 o;
    o.x = (uint32_t)u0 | ((uint32_t)u1 << 16);
    o.y = (uint32_t)u2 | ((uint32_t)u3 << 16);
    ((uint2*)g_Msb)[i] = o;
}

// ---------------- transpose + convert Mo -> MoT e4m3 x128 [n][t] ----------------
__global__ void convT_kernel(const float* __restrict__ Mo) {
    __shared__ float sh[64][33];
    int t0 = blockIdx.x * 64, n0 = blockIdx.y * 32;
    int tx = threadIdx.x, ty = threadIdx.y;
    sh[ty][tx]      = Mo[(size_t)(t0 + ty) * NEE + n0 + tx];
    sh[ty + 32][tx] = Mo[(size_t)(t0 + ty + 32) * NEE + n0 + tx];
    __syncthreads();
    float lo = sh[2 * tx][ty] * SCALE_M, hi = sh[2 * tx + 1][ty] * SCALE_M;
    uint16_t pk; CVT_E4M3X2(pk, hi, lo);
    ((uint16_t*)g_MoTb)[(size_t)(n0 + ty) * (TT_ / 2) + t0 / 2 + tx] = pk;
}

// ---------------- EmbeddingBag + span dot (v2: warp-per-element) ----------------
__device__ __forceinline__ int segsearch(const int* o, int l) {
    int lo = 0, hi = SCC;
    #pragma unroll
    for (int s = 0; s < 8; s++) {
        int mid = (lo + hi) >> 1;
        if (o[mid] <= l) lo = mid + 1; else hi = mid;
    }
    return lo - 1;
}

__global__ void __launch_bounds__(256) emb_dot_kernel(
        const float* __restrict__ emb,
        const int* __restrict__ ids,
        const float* __restrict__ att,
        const int* __restrict__ offs,
        const float* __restrict__ span_embs) {
    int b = blockIdx.x >> 4, chunk = blockIdx.x & 15;
    int tid = threadIdx.x, w = tid >> 5, lane = tid & 31;

    __shared__ float span_s[SS * DD];
    __shared__ int   offs_s[SCC];
    __shared__ float sum1_s[SCC];

    const float4* sp  = (const float4*)(span_embs + (size_t)b * SS * DD);
    float4*       sps = (float4*)span_s;
    #pragma unroll
    for (int i = 0; i < (SS * DD / 4) / 256; i++) sps[tid + i * 256] = sp[tid + i * 256];
    offs_s[tid] = offs[b * SCC + tid];
    sum1_s[tid] = 0.f;
    __syncthreads();

    const int bL   = b * LL;
    const int base = chunk * 128 + w * 16;

    #pragma unroll
    for (int i = 0; i < 16; i += 2) {
        int la = base + i, lb = base + i + 1;
        int   ida = ids[bL + la], idb = ids[bL + lb];
        float wa  = att[bL + la], wb  = att[bL + lb];
        int sega = segsearch(offs_s, la);
        int segb = segsearch(offs_s, lb);
        const float4* ra = (const float4*)(emb + (size_t)ida * DD);
        const float4* rb = (const float4*)(emb + (size_t)idb * DD);
        const float4* sa = (const float4*)(span_s + (sega & 7) * DD);
        const float4* sb = (const float4*)(span_s + (segb & 7) * DD);
        float da = 0.f, db = 0.f;
        #pragma unroll
        for (int j = 0; j < 6; j++) {
            float4 va = ra[lane + 32 * j];
            float4 xa = sa[lane + 32 * j];
            da += va.x * xa.x + va.y * xa.y + va.z * xa.z + va.w * xa.w;
            float4 vb = rb[lane + 32 * j];
            float4 xb = sb[lane + 32 * j];
            db += vb.x * xb.x + vb.y * xb.y + vb.z * xb.z + vb.w * xb.w;
        }
        #pragma unroll
        for (int o = 16; o; o >>= 1) {
            da += __shfl_xor_sync(0xffffffffu, da, o);
            db += __shfl_xor_sync(0xffffffffu, db, o);
        }
        if (lane == 0) {
            atomicAdd(&sum1_s[sega], wa * da);
            atomicAdd(&sum1_s[segb], wb * db);
        }
    }
    __syncthreads();
    atomicAdd(&g_sum1[b * SCC + tid], sum1_s[tid]);
}

// ---------------- fused: softmax chain -> cand -> scatter -> NE softmax -> e5m2 ----------------
__global__ void cand_softmax_kernel(const float* __restrict__ span_embs,
                                    const float* __restrict__ span_w,
                                    const float* __restrict__ span_b,
                                    const int* __restrict__ qid_inds,
                                    float sx0) {
    int b = blockIdx.x, tid = threadIdx.x;
    __shared__ float ent[NEE];
    __shared__ float sh_sum1[256];
    __shared__ float sh_score[8];
    __shared__ float red[8];
    __shared__ float bc;

    #pragma unroll
    for (int i = 0; i < NEE / 256; i++) ent[tid + i * 256] = 0.f;

    int w = tid >> 5, lane = tid & 31;
    {
        const float* se = span_embs + ((size_t)b * SS + w) * DD;
        float d = 0.f;
        for (int i = lane; i < DD; i += 32) d += se[i] * span_w[i];
        #pragma unroll
        for (int o = 16; o; o >>= 1) d += __shfl_xor_sync(0xffffffffu, d, o);
        if (lane == 0) sh_score[w] = d + span_b[0];
    }
    sh_sum1[tid] = g_sum1[b * SCC + tid];
    __syncthreads();

    int c = tid & 31, s = tid >> 5;
    float m = -1e30f;
    #pragma unroll
    for (int s2 = 0; s2 < 8; s2++) m = fmaxf(m, sh_sum1[s2 * 32 + c]);
    float den = 0.f;
    #pragma unroll
    for (int s2 = 0; s2 < 8; s2++) den += expf(sh_sum1[s2 * 32 + c] - m);
    float sm1 = expf(sh_sum1[tid] - m) / den;
    float tv  = sh_score[s] * sm1;

    float bm = tv;
    #pragma unroll
    for (int o = 16; o; o >>= 1) bm = fmaxf(bm, __shfl_xor_sync(0xffffffffu, bm, o));
    if (lane == 0) red[w] = bm;
    __syncthreads();
    if (tid == 0) { float x = red[0]; for (int j = 1; j < 8; j++) x = fmaxf(x, red[j]); bc = x; }
    __syncthreads();
    bm = bc;
    float e = expf(tv - bm);
    float sm = e;
    #pragma unroll
    for (int o = 16; o; o >>= 1) sm += __shfl_xor_sync(0xffffffffu, sm, o);
    __syncthreads();
    if (lane == 0) red[w] = sm;
    __syncthreads();
    if (tid == 0) { float x = 0.f; for (int j = 0; j < 8; j++) x += red[j]; bc = x; }
    __syncthreads();
    float cand = e / bc;

    int qid = qid_inds[b * SCC + tid];
    if (qid < NEE) atomicAdd(&ent[qid], cand);
    __syncthreads();

    float v[NEE / 256];
    m = -1e30f;
    #pragma unroll
    for (int i = 0; i < NEE / 256; i++) { v[i] = ent[tid + i * 256]; m = fmaxf(m, v[i]); }
    #pragma unroll
    for (int o = 16; o; o >>= 1) m = fmaxf(m, __shfl_xor_sync(0xffffffffu, m, o));
    if (lane == 0) red[w] = m;
    __syncthreads();
    if (tid == 0) { float x = red[0]; for (int j = 1; j < 8; j++) x = fmaxf(x, red[j]); bc = x; }
    __syncthreads();
    m = bc;
    float ssum = 0.f;
    #pragma unroll
    for (int i = 0; i < NEE / 256; i++) { v[i] = expf(v[i] - m); ssum += v[i]; }
    #pragma unroll
    for (int o = 16; o; o >>= 1) ssum += __shfl_xor_sync(0xffffffffu, ssum, o);
    __syncthreads();
    if (lane == 0) red[w] = ssum;
    __syncthreads();
    if (tid == 0) { float x = 0.f; for (int j = 0; j < 8; j++) x += red[j]; bc = x; }
    __syncthreads();
    float inv = sx0 / bc;
    uint8_t* orow = g_xb + (size_t)b * NEE;
    #pragma unroll
    for (int i = 0; i < NEE / 256; i++) {
        uint16_t pk; CVT_E5M2X2(pk, 0.f, v[i] * inv);
        orow[tid + i * 256] = (uint8_t)(pk & 0xff);
    }
}

// ---------------- combine 4 split x partials -> e5m2 g_xb ----------------
__global__ void combine_xb_kernel(const float* __restrict__ p0, float cb) {
    size_t i = (size_t)blockIdx.x * 256 + threadIdx.x;   // 4 floats -> 4 bytes
    const size_t XS = (size_t)BB * NEE;
    float4 v = ((const float4*)p0)[i];
    #pragma unroll
    for (int k = 1; k < KSPLIT; k++) {
        float4 w2 = ((const float4*)(p0 + k * XS))[i];
        v.x += w2.x; v.y += w2.y; v.z += w2.z; v.w += w2.w;
    }
    uint16_t u0, u1;
    CVT_E5M2X2(u0, v.y * cb, v.x * cb);
    CVT_E5M2X2(u1, v.w * cb, v.z * cb);
    ((uint32_t*)g_xb)[i] = (uint32_t)u0 | ((uint32_t)u1 << 16);
}

// ---------------- q = qn_emb @ red_w.T + red_b ----------------
__global__ void q_kernel(const float* __restrict__ qn,
                         const float* __restrict__ rw,
                         const float* __restrict__ rb) {
    int b = blockIdx.x;
    int w = threadIdx.x >> 5, lane = threadIdx.x & 31;
    const float* q = qn + (size_t)b * DD;
    for (int h = w; h < HH; h += 8) {
        const float* r = rw + (size_t)h * DD;
        float d = 0.f;
        for (int i = lane; i < DD; i += 32) d += q[i] * r[i];
        #pragma unroll
        for (int o = 16; o; o >>= 1) d += __shfl_xor_sync(0xffffffffu, d, o);
        if (lane == 0) g_h[b * 320 + h] = d + rb[h];
    }
}

// ---------------- per-hop r = softmax(h@W.T+b), att logit ----------------
__global__ void r_kernel(const float* __restrict__ W, const float* __restrict__ bias,
                         const float* __restrict__ aw, const float* __restrict__ ab, int hop) {
    int b = blockIdx.x, tid = threadIdx.x;
    int Wd = HH * (hop + 1);
    __shared__ float sh_h[240];
    __shared__ float sh_v[80];
    for (int i = tid; i < Wd; i += 128) sh_h[i] = g_h[b * 320 + i];
    __syncthreads();
    if (tid < 80) {
        float a = bias[tid];
        const float* row = W + (size_t)tid * Wd;
        for (int i = 0; i < Wd; i++) a += sh_h[i] * row[i];
        sh_v[tid] = a;
    } else if (tid == 80) {
        float a = ab[0];
        for (int i = 0; i < Wd; i++) a += sh_h[i] * aw[i];
        g_att[b * 3 + hop] = a;
    }
    __syncthreads();
    float m = -1e30f;
    for (int i = 0; i < 80; i++) m = fmaxf(m, sh_v[i]);
    float s = 0.f;
    for (int i = 0; i < 80; i++) s += expf(sh_v[i] - m);
    if (tid < 80) g_h[b * 320 + Wd + tid] = expf(sh_v[tid] - m) / s;
}

// =====================================================================
// FP8 MMA GEMM: D[m][c] = sum_k A[m][k] * B[c][k]
//   A: e4m3 [8192][8192];  B: e5m2 [32][8192]
//   CTA: 128 M x 32 N; split-K x4 (2048 K each); k-chunk 128 elems = 128B rows
//   Identical smem layout/swizzle/ldmatrix addressing as the bf16 version
//   (fp8 k32 fragments are b16-unit-identical to f16 k16 fragments).
// =====================================================================
#define KCHUNK 128
#define NIT    16   // 2048 / 128
#define SA_STAGE 16384
#define SB_STAGE 4096
#define GEMM_SMEM (4 * (SA_STAGE + SB_STAGE))

template<bool TRANS_OUT>
__global__ void __launch_bounds__(256) fp8_gemm_kernel(
    const uint8_t* __restrict__ A,
    const uint8_t* __restrict__ Bb,
    float* __restrict__ OutBase, size_t out_split_stride) {

    extern __shared__ uint8_t smem[];
    const uint32_t sAb = smem_to_u32(smem);
    const uint32_t sBb = sAb + 4 * SA_STAGE;

    const int tid  = threadIdx.x;
    const int wid  = tid >> 5;
    const int lane = tid & 31;
    const int mbase  = blockIdx.x * 128;
    const int kstart = blockIdx.y * (KCHUNK * NIT);
    float* Out = OutBase + blockIdx.y * out_split_stride;

    const uint8_t* Ab = A + (size_t)mbase * 8192 + kstart;
    const uint8_t* Bx = Bb + kstart;

    const int arow = tid >> 3;
    const int ac   = tid & 7;
    auto prefetch = [&](int it) {
        const int stage = it & 3;
        const uint32_t sa = sAb + stage * SA_STAGE;
        const uint32_t sb = sBb + stage * SB_STAGE;
        const uint8_t* ga = Ab + it * KCHUNK;
        #pragma unroll
        for (int j = 0; j < 4; j++) {
            int row = arow + j * 32;
            uint32_t dst = sa + row * 128 + ((ac ^ (row & 7)) << 4);
            CP_ASYNC16(dst, ga + (size_t)row * 8192 + ac * 16);
        }
        uint32_t dstb = sb + arow * 128 + ((ac ^ (arow & 7)) << 4);
        CP_ASYNC16(dstb, Bx + (size_t)arow * 8192 + it * KCHUNK + ac * 16);
    };

    prefetch(0); CP_COMMIT();
    prefetch(1); CP_COMMIT();
    prefetch(2); CP_COMMIT();

    float acc[4][4];
    #pragma unroll
    for (int j = 0; j < 4; j++)
        #pragma unroll
        for (int i = 0; i < 4; i++) acc[j][i] = 0.f;

    const int a_quad = lane >> 3;
    const int a_rloc = wid * 16 + (lane & 7) + (a_quad & 1) * 8;
    const int a_cke  = a_quad >> 1;
    const int b_n    = ((lane >> 4) * 8) + (lane & 7);
    const int b_cke  = (lane >> 3) & 1;

    for (int it = 0; it < NIT; it++) {
        if (it + 2 < NIT) { CP_WAIT(2); }
        else if (it + 1 < NIT) { CP_WAIT(1); }
        else { CP_WAIT(0); }
        __syncthreads();
        if (it + 3 < NIT) { prefetch(it + 3); CP_COMMIT(); }

        const int stage = it & 3;
        const uint32_t sa = sAb + stage * SA_STAGE;
        const uint32_t sb = sBb + stage * SB_STAGE;

        #pragma unroll
        for (int s = 0; s < 4; s++) {   // 4 k32-steps per 128-elem chunk
            uint32_t a0, a1, a2, a3;
            {
                int c = s * 2 + a_cke;
                uint32_t addr = sa + a_rloc * 128 + ((c ^ (a_rloc & 7)) << 4);
                LDMATRIX_X4(a0, a1, a2, a3, addr);
            }
            uint32_t bL[4], bH[4];
            {
                int c = s * 2 + b_cke;
                uint32_t addr0 = sb + b_n * 128 + ((c ^ (b_n & 7)) << 4);
                LDMATRIX_X4(bL[0], bL[1], bL[2], bL[3], addr0);
                int n1 = 16 + b_n;
                uint32_t addr1 = sb + n1 * 128 + ((c ^ (n1 & 7)) << 4);
                LDMATRIX_X4(bH[0], bH[1], bH[2], bH[3], addr1);
            }
            MMA_FP8(acc[0], a0, a1, a2, a3, bL[0], bL[1]);
            MMA_FP8(acc[1], a0, a1, a2, a3, bL[2], bL[3]);
            MMA_FP8(acc[2], a0, a1, a2, a3, bH[0], bH[1]);
            MMA_FP8(acc[3], a0, a1, a2, a3, bH[2], bH[3]);
        }
    }

    if (!TRANS_OUT) {
        const int row0 = mbase + wid * 16 + (lane >> 2);
        #pragma unroll
        for (int j = 0; j < 4; j++) {
            int col = j * 8 + (lane & 3) * 2;
            *(float2*)(Out + (size_t)row0 * 32 + col) = make_float2(acc[j][0], acc[j][1]);
            *(float2*)(Out + (size_t)(row0 + 8) * 32 + col) = make_float2(acc[j][2], acc[j][3]);
        }
    } else {
        float* ep = (float*)smem;
        __syncthreads();
        const int mloc = wid * 16 + (lane >> 2);
        #pragma unroll
        for (int j = 0; j < 4; j++) {
            int col = j * 8 + (lane & 3) * 2;
            ep[col * 128 + mloc]           = acc[j][0];
            ep[(col + 1) * 128 + mloc]     = acc[j][1];
            ep[col * 128 + mloc + 8]       = acc[j][2];
            ep[(col + 1) * 128 + mloc + 8] = acc[j][3];
        }
        __syncthreads();
        #pragma unroll
        for (int i = 0; i < 16; i++) {
            int idx = tid + i * 256;
            int cc = idx >> 7, mm = idx & 127;
            Out[(size_t)cc * 8192 + mbase + mm] = ep[idx];
        }
    }
}

// ---------------- z: zb[b][t] = e5m2( (sum_ks y)[t][b] * dot(Mp[t], r[b]) * cz ) ----------------
__global__ void z_kernel(const float* __restrict__ Mp, int hop, float cz) {
    __shared__ float rsh[32][81];
    __shared__ float ztile[32][8];
    int tid = threadIdx.x;
    for (int i = tid; i < BB * HH; i += 256) {
        int bb = i / HH, h = i % HH;
        rsh[bb][h] = g_h[bb * 320 + HH * (hop + 1) + h];
    }
    __syncthreads();
    int w = tid >> 5, lane = tid & 31;
    int t = blockIdx.x * 8 + w;
    const float* mp = Mp + (size_t)t * HH;
    float p = 0.f;
    #pragma unroll
    for (int h = 0; h < HH; h++) p += mp[h] * rsh[lane][h];
    size_t off = (size_t)t * BB + lane;
    float ysum = 0.f;
    #pragma unroll
    for (int k = 0; k < KSPLIT; k++) ysum += g_y[k][off];
    ztile[lane][w] = ysum * p * cz;
    __syncthreads();
    int b = tid >> 3, j = tid & 7;
    uint16_t pk; CVT_E5M2X2(pk, 0.f, ztile[b][j]);
    g_zb[(size_t)b * TT_ + blockIdx.x * 8 + j] = (uint8_t)(pk & 0xff);
}

// ---------------- final ----------------
__global__ void final_kernel(float* __restrict__ out, float f0, float f1, float f2) {
    int b = blockIdx.y;
    int n = blockIdx.x * 256 + threadIdx.x;
    float l0 = g_att[b * 3 + 0], l1 = g_att[b * 3 + 1], l2 = g_att[b * 3 + 2];
    float m = fmaxf(l0, fmaxf(l1, l2));
    float e0 = expf(l0 - m), e1 = expf(l1 - m), e2 = expf(l2 - m);
    float inv = 1.f / (e0 + e1 + e2);
    size_t off = (size_t)b * NEE + n;
    float x0 = 0.f, x1 = 0.f, x2 = 0.f;
    #pragma unroll
    for (int k = 0; k < KSPLIT; k++) {
        x0 += g_xp[0][k][off];
        x1 += g_xp[1][k][off];
        x2 += g_xp[2][k][off];
    }
    float v = x0 * f0 * e0 + x1 * f1 * e1 + x2 * f2 * e2;
    out[off] = 1.f / (1.f + expf(-v * inv));
}

// ---------------- launch ----------------
extern "C" void kernel_launch(void* const* d_in, const int* in_sizes, int n_in,
                              void* d_out, int out_size) {
    const float* span_embs = (const float*)d_in[0];
    const float* attention = (const float*)d_in[1];
    const float* qn_emb    = (const float*)d_in[2];
    const int*   trip_ids  = (const int*)  d_in[3];
    const int*   offsets   = (const int*)  d_in[4];
    const int*   qid_inds  = (const int*)  d_in[5];
    const float* emb_table = (const float*)d_in[6];
    const float* span_w    = (const float*)d_in[7];
    const float* span_b    = (const float*)d_in[8];
    const float* red_w     = (const float*)d_in[9];
    const float* red_b     = (const float*)d_in[10];
    const float* Ms        = (const float*)d_in[11];
    const float* Mo        = (const float*)d_in[12];
    const float* Mp        = (const float*)d_in[13];
    const float* inf_w[3]  = {(const float*)d_in[14], (const float*)d_in[16], (const float*)d_in[18]};
    const float* inf_b[3]  = {(const float*)d_in[15], (const float*)d_in[17], (const float*)d_in[19]};
    const float* att_w[3]  = {(const float*)d_in[20], (const float*)d_in[22], (const float*)d_in[24]};
    const float* att_b[3]  = {(const float*)d_in[21], (const float*)d_in[23], (const float*)d_in[25]};
    float* out = (float*)d_out;

    cudaFuncSetAttribute(fp8_gemm_kernel<false>,
                         cudaFuncAttributeMaxDynamicSharedMemorySize, GEMM_SMEM);
    cudaFuncSetAttribute(fp8_gemm_kernel<true>,
                         cudaFuncAttributeMaxDynamicSharedMemorySize, GEMM_SMEM);

    float *py, *pxp;
    cudaGetSymbolAddress((void**)&py,  g_y);
    cudaGetSymbolAddress((void**)&pxp, g_xp);
    uint8_t *pMsb, *pMoT, *pxb, *pzb;
    cudaGetSymbolAddress((void**)&pMsb, g_Msb);
    cudaGetSymbolAddress((void**)&pMoT, g_MoTb);
    cudaGetSymbolAddress((void**)&pxb,  g_xb);
    cudaGetSymbolAddress((void**)&pzb,  g_zb);

    const size_t YS = (size_t)TT_ * BB;
    const size_t XS = (size_t)BB * NEE;

    // scale schedule (powers of 2):  SX = {2^8, 2^26, 2^33};  SZ = {2^18, 2^24, 2^30}
    const float SX0 = 256.f;
    const float CZ[3] = { 8.f, 1.f / 512.f, 1.f / 1024.f };        // SZ/(128*SX)
    const float CB[3] = { 0.f, 2.f, 4.f };                          // SX/(128*SZ_prev)
    const float FX[3] = { 1.f / 33554432.f,                         // 1/(128*2^18) = 2^-25
                          1.f / 2147483648.f,                       // 2^-31
                          1.f / 137438953472.f };                   // 2^-37

    // slot #4 = fp8 GEMM1 (profiler captures launch #4)
    convMs_kernel<<<32768, 256>>>(Ms);                              // also zeroes g_sum1
    emb_dot_kernel<<<BB * 16, 256>>>(emb_table, trip_ids, attention, offsets, span_embs);
    cand_softmax_kernel<<<BB, 256>>>(span_embs, span_w, span_b, qid_inds, SX0);
    fp8_gemm_kernel<false><<<dim3(64, KSPLIT), 256, GEMM_SMEM>>>(pMsb, pxb, py, YS);
    convT_kernel<<<dim3(TT_ / 64, NEE / 32), dim3(32, 32)>>>(Mo);
    q_kernel<<<BB, 256>>>(qn_emb, red_w, red_b);

    for (int hop = 0; hop < HOPS; hop++) {
        r_kernel<<<BB, 128>>>(inf_w[hop], inf_b[hop], att_w[hop], att_b[hop], hop);
        if (hop > 0) {
            combine_xb_kernel<<<256, 256>>>(pxp + (size_t)(hop - 1) * KSPLIT * XS, CB[hop]);
            fp8_gemm_kernel<false><<<dim3(64, KSPLIT), 256, GEMM_SMEM>>>(pMsb, pxb, py, YS);
        }
        z_kernel<<<TT_ / 8, 256>>>(Mp, hop, CZ[hop]);
        fp8_gemm_kernel<true><<<dim3(64, KSPLIT), 256, GEMM_SMEM>>>(
            pMoT, pzb, pxp + (size_t)hop * KSPLIT * XS, XS);
    }
    final_kernel<<<dim3(NEE / 256, BB), 256>>>(out, FX[0], FX[1], FX[2]);
}

// round 10
// speedup vs baseline: 1.1408x; 1.0079x over previous
#include <cuda_runtime.h>
#include <cuda_bf16.h>
#include <cstdint>

// ---------------- model constants ----------------
#define BB   32
#define SS   8
#define DD   768
#define NEE  8192
#define TT_  8192
#define HH   80
#define LL   2048
#define SCC  256
#define HOPS 3
#define KSPLIT 4

// ---------------- PTX helpers ----------------
__device__ __forceinline__ uint32_t smem_to_u32(const void* smem_ptr) {
    uint32_t addr;
    asm("{ .reg .u64 tmp; cvta.to.shared.u64 tmp, %1; cvt.u32.u64 %0, tmp; }"
        : "=r"(addr) : "l"(smem_ptr));
    return addr;
}
#define CP_ASYNC16(dst_u32, src_ptr) \
    asm volatile("cp.async.cg.shared.global [%0], [%1], 16;" :: "r"(dst_u32), "l"(src_ptr))
#define CP_COMMIT() asm volatile("cp.async.commit_group;" ::: "memory")
#define CP_WAIT(n)  asm volatile("cp.async.wait_group %0;" :: "n"(n) : "memory")
#define LDMATRIX_X4(r0, r1, r2, r3, addr) \
    asm volatile("ldmatrix.sync.aligned.m8n8.x4.shared.b16 {%0,%1,%2,%3}, [%4];" \
        : "=r"(r0), "=r"(r1), "=r"(r2), "=r"(r3) : "r"(addr))
// fp8 MMA: A=e4m3 (matrix), B=e5m2 (activation), fp32 accum
#define MMA_FP8(c, a0, a1, a2, a3, b0, b1) \
    asm volatile("mma.sync.aligned.m16n8k32.row.col.f32.e4m3.e5m2.f32 " \
        "{%0,%1,%2,%3}, {%4,%5,%6,%7}, {%8,%9}, {%0,%1,%2,%3};" \
        : "+f"((c)[0]), "+f"((c)[1]), "+f"((c)[2]), "+f"((c)[3]) \
        : "r"(a0), "r"(a1), "r"(a2), "r"(a3), "r"(b0), "r"(b1))
#define CVT_E4M3X2(r, hi, lo) \
    asm("cvt.rn.satfinite.e4m3x2.f32 %0, %1, %2;" : "=h"(r) : "f"(hi), "f"(lo))
#define CVT_E5M2X2(r, hi, lo) \
    asm("cvt.rn.satfinite.e5m2x2.f32 %0, %1, %2;" : "=h"(r) : "f"(hi), "f"(lo))

// ---------------- scaling constants (power-of-2, tracked symbolically) ----------------
// SM = 128 (matrices).  SX[hop] for x fed to GEMM1; SZ[hop] for z fed to GEMM2.
// CZ[hop]  = SZ[hop] / (SM*SX[hop])        (applied in z_kernel)
// CB[hop]  = SX[hop] / (SM*SZ[hop-1])      (applied in combine_xb, hop>=1)
// FX[hop]  = 1 / (SM*SZ[hop])              (applied in final)
#define SCALE_M 128.0f

// ---------------- scratch (device globals) ----------------
__device__ float g_sum1[BB * SCC];
__device__ __align__(16) uint8_t g_xb[BB * NEE];          // x, e5m2 scaled
__device__ float g_y[KSPLIT][TT_ * BB];                   // y k-split partials (fp32, scaled)
__device__ __align__(16) uint8_t g_zb[BB * TT_];          // z, e5m2 scaled
__device__ float g_xp[HOPS][KSPLIT][BB * NEE];            // x partials (fp32, scaled)
__device__ float g_h[BB * 320];
__device__ float g_att[BB * 3];
__device__ __align__(16) uint8_t g_Msb[(size_t)TT_ * NEE];  // Ms e4m3 x128, row-major [t][n]
__device__ __align__(16) uint8_t g_MoTb[(size_t)NEE * TT_]; // Mo^T e4m3 x128, [n][t]

// ---------------- Ms fp32 -> e4m3 x128 (+ zero g_sum1 in blocks 0..31) ----------------
__global__ void convMs_kernel(const float* __restrict__ Ms) {
    if (blockIdx.x < 32) g_sum1[blockIdx.x * 256 + threadIdx.x] = 0.f;
    size_t i = (size_t)blockIdx.x * 256 + threadIdx.x;   // 8 elements each
    float4 v0 = ((const float4*)Ms)[2 * i], v1 = ((const float4*)Ms)[2 * i + 1];
    uint16_t u0, u1, u2, u3;
    CVT_E4M3X2(u0, v0.y * SCALE_M, v0.x * SCALE_M);
    CVT_E4M3X2(u1, v0.w * SCALE_M, v0.z * SCALE_M);
    CVT_E4M3X2(u2, v1.y * SCALE_M, v1.x * SCALE_M);
    CVT_E4M3X2(u3, v1.w * SCALE_M, v1.z * SCALE_M);
    uint2 o;
    o.x = (uint32_t)u0 | ((uint32_t)u1 << 16);
    o.y = (uint32_t)u2 | ((uint32_t)u3 << 16);
    ((uint2*)g_Msb)[i] = o;
}

// ---------------- transpose + convert Mo -> MoT e4m3 x128 [n][t] ----------------
__global__ void convT_kernel(const float* __restrict__ Mo) {
    __shared__ float sh[64][33];
    int t0 = blockIdx.x * 64, n0 = blockIdx.y * 32;
    int tx = threadIdx.x, ty = threadIdx.y;
    sh[ty][tx]      = Mo[(size_t)(t0 + ty) * NEE + n0 + tx];
    sh[ty + 32][tx] = Mo[(size_t)(t0 + ty + 32) * NEE + n0 + tx];
    __syncthreads();
    float lo = sh[2 * tx][ty] * SCALE_M, hi = sh[2 * tx + 1][ty] * SCALE_M;
    uint16_t pk; CVT_E4M3X2(pk, hi, lo);
    ((uint16_t*)g_MoTb)[(size_t)(n0 + ty) * (TT_ / 2) + t0 / 2 + tx] = pk;
}

// ---------------- EmbeddingBag + span dot (v2: warp-per-element) ----------------
__device__ __forceinline__ int segsearch(const int* o, int l) {
    int lo = 0, hi = SCC;
    #pragma unroll
    for (int s = 0; s < 8; s++) {
        int mid = (lo + hi) >> 1;
        if (o[mid] <= l) lo = mid + 1; else hi = mid;
    }
    return lo - 1;
}

__global__ void __launch_bounds__(256) emb_dot_kernel(
        const float* __restrict__ emb,
        const int* __restrict__ ids,
        const float* __restrict__ att,
        const int* __restrict__ offs,
        const float* __restrict__ span_embs) {
    int b = blockIdx.x >> 4, chunk = blockIdx.x & 15;
    int tid = threadIdx.x, w = tid >> 5, lane = tid & 31;

    __shared__ float span_s[SS * DD];
    __shared__ int   offs_s[SCC];
    __shared__ float sum1_s[SCC];

    const float4* sp  = (const float4*)(span_embs + (size_t)b * SS * DD);
    float4*       sps = (float4*)span_s;
    #pragma unroll
    for (int i = 0; i < (SS * DD / 4) / 256; i++) sps[tid + i * 256] = sp[tid + i * 256];
    offs_s[tid] = offs[b * SCC + tid];
    sum1_s[tid] = 0.f;
    __syncthreads();

    const int bL   = b * LL;
    const int base = chunk * 128 + w * 16;

    #pragma unroll
    for (int i = 0; i < 16; i += 2) {
        int la = base + i, lb = base + i + 1;
        int   ida = ids[bL + la], idb = ids[bL + lb];
        float wa  = att[bL + la], wb  = att[bL + lb];
        int sega = segsearch(offs_s, la);
        int segb = segsearch(offs_s, lb);
        const float4* ra = (const float4*)(emb + (size_t)ida * DD);
        const float4* rb = (const float4*)(emb + (size_t)idb * DD);
        const float4* sa = (const float4*)(span_s + (sega & 7) * DD);
        const float4* sb = (const float4*)(span_s + (segb & 7) * DD);
        float da = 0.f, db = 0.f;
        #pragma unroll
        for (int j = 0; j < 6; j++) {
            float4 va = ra[lane + 32 * j];
            float4 xa = sa[lane + 32 * j];
            da += va.x * xa.x + va.y * xa.y + va.z * xa.z + va.w * xa.w;
            float4 vb = rb[lane + 32 * j];
            float4 xb = sb[lane + 32 * j];
            db += vb.x * xb.x + vb.y * xb.y + vb.z * xb.z + vb.w * xb.w;
        }
        #pragma unroll
        for (int o = 16; o; o >>= 1) {
            da += __shfl_xor_sync(0xffffffffu, da, o);
            db += __shfl_xor_sync(0xffffffffu, db, o);
        }
        if (lane == 0) {
            atomicAdd(&sum1_s[sega], wa * da);
            atomicAdd(&sum1_s[segb], wb * db);
        }
    }
    __syncthreads();
    atomicAdd(&g_sum1[b * SCC + tid], sum1_s[tid]);
}

// ---------------- fused: softmax chain -> cand -> scatter -> NE softmax -> e5m2 ----------------
__global__ void cand_softmax_kernel(const float* __restrict__ span_embs,
                                    const float* __restrict__ span_w,
                                    const float* __restrict__ span_b,
                                    const int* __restrict__ qid_inds,
                                    float sx0) {
    int b = blockIdx.x, tid = threadIdx.x;
    __shared__ float ent[NEE];
    __shared__ float sh_sum1[256];
    __shared__ float sh_score[8];
    __shared__ float red[8];
    __shared__ float bc;

    #pragma unroll
    for (int i = 0; i < NEE / 256; i++) ent[tid + i * 256] = 0.f;

    int w = tid >> 5, lane = tid & 31;
    {
        const float* se = span_embs + ((size_t)b * SS + w) * DD;
        float d = 0.f;
        for (int i = lane; i < DD; i += 32) d += se[i] * span_w[i];
        #pragma unroll
        for (int o = 16; o; o >>= 1) d += __shfl_xor_sync(0xffffffffu, d, o);
        if (lane == 0) sh_score[w] = d + span_b[0];
    }
    sh_sum1[tid] = g_sum1[b * SCC + tid];
    __syncthreads();

    int c = tid & 31, s = tid >> 5;
    float m = -1e30f;
    #pragma unroll
    for (int s2 = 0; s2 < 8; s2++) m = fmaxf(m, sh_sum1[s2 * 32 + c]);
    float den = 0.f;
    #pragma unroll
    for (int s2 = 0; s2 < 8; s2++) den += expf(sh_sum1[s2 * 32 + c] - m);
    float sm1 = expf(sh_sum1[tid] - m) / den;
    float tv  = sh_score[s] * sm1;

    float bm = tv;
    #pragma unroll
    for (int o = 16; o; o >>= 1) bm = fmaxf(bm, __shfl_xor_sync(0xffffffffu, bm, o));
    if (lane == 0) red[w] = bm;
    __syncthreads();
    if (tid == 0) { float x = red[0]; for (int j = 1; j < 8; j++) x = fmaxf(x, red[j]); bc = x; }
    __syncthreads();
    bm = bc;
    float e = expf(tv - bm);
    float sm = e;
    #pragma unroll
    for (int o = 16; o; o >>= 1) sm += __shfl_xor_sync(0xffffffffu, sm, o);
    __syncthreads();
    if (lane == 0) red[w] = sm;
    __syncthreads();
    if (tid == 0) { float x = 0.f; for (int j = 0; j < 8; j++) x += red[j]; bc = x; }
    __syncthreads();
    float cand = e / bc;

    int qid = qid_inds[b * SCC + tid];
    if (qid < NEE) atomicAdd(&ent[qid], cand);
    __syncthreads();

    float v[NEE / 256];
    m = -1e30f;
    #pragma unroll
    for (int i = 0; i < NEE / 256; i++) { v[i] = ent[tid + i * 256]; m = fmaxf(m, v[i]); }
    #pragma unroll
    for (int o = 16; o; o >>= 1) m = fmaxf(m, __shfl_xor_sync(0xffffffffu, m, o));
    if (lane == 0) red[w] = m;
    __syncthreads();
    if (tid == 0) { float x = red[0]; for (int j = 1; j < 8; j++) x = fmaxf(x, red[j]); bc = x; }
    __syncthreads();
    m = bc;
    float ssum = 0.f;
    #pragma unroll
    for (int i = 0; i < NEE / 256; i++) { v[i] = expf(v[i] - m); ssum += v[i]; }
    #pragma unroll
    for (int o = 16; o; o >>= 1) ssum += __shfl_xor_sync(0xffffffffu, ssum, o);
    __syncthreads();
    if (lane == 0) red[w] = ssum;
    __syncthreads();
    if (tid == 0) { float x = 0.f; for (int j = 0; j < 8; j++) x += red[j]; bc = x; }
    __syncthreads();
    float inv = sx0 / bc;
    uint8_t* orow = g_xb + (size_t)b * NEE;
    #pragma unroll
    for (int i = 0; i < NEE / 256; i++) {
        uint16_t pk; CVT_E5M2X2(pk, 0.f, v[i] * inv);
        orow[tid + i * 256] = (uint8_t)(pk & 0xff);
    }
}

// ---------------- combine 4 split x partials -> e5m2 g_xb ----------------
__global__ void combine_xb_kernel(const float* __restrict__ p0, float cb) {
    size_t i = (size_t)blockIdx.x * 256 + threadIdx.x;   // 4 floats -> 4 bytes
    const size_t XS = (size_t)BB * NEE;
    float4 v = ((const float4*)p0)[i];
    #pragma unroll
    for (int k = 1; k < KSPLIT; k++) {
        float4 w2 = ((const float4*)(p0 + k * XS))[i];
        v.x += w2.x; v.y += w2.y; v.z += w2.z; v.w += w2.w;
    }
    uint16_t u0, u1;
    CVT_E5M2X2(u0, v.y * cb, v.x * cb);
    CVT_E5M2X2(u1, v.w * cb, v.z * cb);
    ((uint32_t*)g_xb)[i] = (uint32_t)u0 | ((uint32_t)u1 << 16);
}

// ---------------- q = qn_emb @ red_w.T + red_b ----------------
__global__ void q_kernel(const float* __restrict__ qn,
                         const float* __restrict__ rw,
                         const float* __restrict__ rb) {
    int b = blockIdx.x;
    int w = threadIdx.x >> 5, lane = threadIdx.x & 31;
    const float* q = qn + (size_t)b * DD;
    for (int h = w; h < HH; h += 8) {
        const float* r = rw + (size_t)h * DD;
        float d = 0.f;
        for (int i = lane; i < DD; i += 32) d += q[i] * r[i];
        #pragma unroll
        for (int o = 16; o; o >>= 1) d += __shfl_xor_sync(0xffffffffu, d, o);
        if (lane == 0) g_h[b * 320 + h] = d + rb[h];
    }
}

// ---------------- per-hop r = softmax(h@W.T+b), att logit ----------------
__global__ void r_kernel(const float* __restrict__ W, const float* __restrict__ bias,
                         const float* __restrict__ aw, const float* __restrict__ ab, int hop) {
    int b = blockIdx.x, tid = threadIdx.x;
    int Wd = HH * (hop + 1);
    __shared__ float sh_h[240];
    __shared__ float sh_v[80];
    for (int i = tid; i < Wd; i += 128) sh_h[i] = g_h[b * 320 + i];
    __syncthreads();
    if (tid < 80) {
        float a = bias[tid];
        const float* row = W + (size_t)tid * Wd;
        for (int i = 0; i < Wd; i++) a += sh_h[i] * row[i];
        sh_v[tid] = a;
    } else if (tid == 80) {
        float a = ab[0];
        for (int i = 0; i < Wd; i++) a += sh_h[i] * aw[i];
        g_att[b * 3 + hop] = a;
    }
    __syncthreads();
    float m = -1e30f;
    for (int i = 0; i < 80; i++) m = fmaxf(m, sh_v[i]);
    float s = 0.f;
    for (int i = 0; i < 80; i++) s += expf(sh_v[i] - m);
    if (tid < 80) g_h[b * 320 + Wd + tid] = expf(sh_v[tid] - m) / s;
}

// =====================================================================
// FP8 MMA GEMM: D[m][c] = sum_k A[m][k] * B[c][k]
//   A: e4m3 [8192][8192];  B: e5m2 [32][8192]
//   CTA: 128 M x 32 N; split-K x4 (2048 K each); k-chunk 128 elems = 128B rows
//   Identical smem layout/swizzle/ldmatrix addressing as the bf16 version
//   (fp8 k32 fragments are b16-unit-identical to f16 k16 fragments).
// =====================================================================
#define KCHUNK 128
#define NIT    16   // 2048 / 128
#define SA_STAGE 16384
#define SB_STAGE 4096
#define GEMM_SMEM (4 * (SA_STAGE + SB_STAGE))

template<bool TRANS_OUT>
__global__ void __launch_bounds__(256) fp8_gemm_kernel(
    const uint8_t* __restrict__ A,
    const uint8_t* __restrict__ Bb,
    float* __restrict__ OutBase, size_t out_split_stride) {

    extern __shared__ uint8_t smem[];
    const uint32_t sAb = smem_to_u32(smem);
    const uint32_t sBb = sAb + 4 * SA_STAGE;

    const int tid  = threadIdx.x;
    const int wid  = tid >> 5;
    const int lane = tid & 31;
    const int mbase  = blockIdx.x * 128;
    const int kstart = blockIdx.y * (KCHUNK * NIT);
    float* Out = OutBase + blockIdx.y * out_split_stride;

    const uint8_t* Ab = A + (size_t)mbase * 8192 + kstart;
    const uint8_t* Bx = Bb + kstart;

    const int arow = tid >> 3;
    const int ac   = tid & 7;
    auto prefetch = [&](int it) {
        const int stage = it & 3;
        const uint32_t sa = sAb + stage * SA_STAGE;
        const uint32_t sb = sBb + stage * SB_STAGE;
        const uint8_t* ga = Ab + it * KCHUNK;
        #pragma unroll
        for (int j = 0; j < 4; j++) {
            int row = arow + j * 32;
            uint32_t dst = sa + row * 128 + ((ac ^ (row & 7)) << 4);
            CP_ASYNC16(dst, ga + (size_t)row * 8192 + ac * 16);
        }
        uint32_t dstb = sb + arow * 128 + ((ac ^ (arow & 7)) << 4);
        CP_ASYNC16(dstb, Bx + (size_t)arow * 8192 + it * KCHUNK + ac * 16);
    };

    prefetch(0); CP_COMMIT();
    prefetch(1); CP_COMMIT();
    prefetch(2); CP_COMMIT();

    float acc[4][4];
    #pragma unroll
    for (int j = 0; j < 4; j++)
        #pragma unroll
        for (int i = 0; i < 4; i++) acc[j][i] = 0.f;

    const int a_quad = lane >> 3;
    const int a_rloc = wid * 16 + (lane & 7) + (a_quad & 1) * 8;
    const int a_cke  = a_quad >> 1;
    const int b_n    = ((lane >> 4) * 8) + (lane & 7);
    const int b_cke  = (lane >> 3) & 1;

    for (int it = 0; it < NIT; it++) {
        if (it + 2 < NIT) { CP_WAIT(2); }
        else if (it + 1 < NIT) { CP_WAIT(1); }
        else { CP_WAIT(0); }
        __syncthreads();
        if (it + 3 < NIT) { prefetch(it + 3); CP_COMMIT(); }

        const int stage = it & 3;
        const uint32_t sa = sAb + stage * SA_STAGE;
        const uint32_t sb = sBb + stage * SB_STAGE;

        #pragma unroll
        for (int s = 0; s < 4; s++) {   // 4 k32-steps per 128-elem chunk
            uint32_t a0, a1, a2, a3;
            {
                int c = s * 2 + a_cke;
                uint32_t addr = sa + a_rloc * 128 + ((c ^ (a_rloc & 7)) << 4);
                LDMATRIX_X4(a0, a1, a2, a3, addr);
            }
            uint32_t bL[4], bH[4];
            {
                int c = s * 2 + b_cke;
                uint32_t addr0 = sb + b_n * 128 + ((c ^ (b_n & 7)) << 4);
                LDMATRIX_X4(bL[0], bL[1], bL[2], bL[3], addr0);
                int n1 = 16 + b_n;
                uint32_t addr1 = sb + n1 * 128 + ((c ^ (n1 & 7)) << 4);
                LDMATRIX_X4(bH[0], bH[1], bH[2], bH[3], addr1);
            }
            MMA_FP8(acc[0], a0, a1, a2, a3, bL[0], bL[1]);
            MMA_FP8(acc[1], a0, a1, a2, a3, bL[2], bL[3]);
            MMA_FP8(acc[2], a0, a1, a2, a3, bH[0], bH[1]);
            MMA_FP8(acc[3], a0, a1, a2, a3, bH[2], bH[3]);
        }
    }

    if (!TRANS_OUT) {
        const int row0 = mbase + wid * 16 + (lane >> 2);
        #pragma unroll
        for (int j = 0; j < 4; j++) {
            int col = j * 8 + (lane & 3) * 2;
            *(float2*)(Out + (size_t)row0 * 32 + col) = make_float2(acc[j][0], acc[j][1]);
            *(float2*)(Out + (size_t)(row0 + 8) * 32 + col) = make_float2(acc[j][2], acc[j][3]);
        }
    } else {
        float* ep = (float*)smem;
        __syncthreads();
        const int mloc = wid * 16 + (lane >> 2);
        #pragma unroll
        for (int j = 0; j < 4; j++) {
            int col = j * 8 + (lane & 3) * 2;
            ep[col * 128 + mloc]           = acc[j][0];
            ep[(col + 1) * 128 + mloc]     = acc[j][1];
            ep[col * 128 + mloc + 8]       = acc[j][2];
            ep[(col + 1) * 128 + mloc + 8] = acc[j][3];
        }
        __syncthreads();
        #pragma unroll
        for (int i = 0; i < 16; i++) {
            int idx = tid + i * 256;
            int cc = idx >> 7, mm = idx & 127;
            Out[(size_t)cc * 8192 + mbase + mm] = ep[idx];
        }
    }
}

// ---------------- z: zb[b][t] = e5m2( (sum_ks y)[t][b] * dot(Mp[t], r[b]) * cz ) ----------------
__global__ void z_kernel(const float* __restrict__ Mp, int hop, float cz) {
    __shared__ float rsh[32][81];
    __shared__ float ztile[32][8];
    int tid = threadIdx.x;
    for (int i = tid; i < BB * HH; i += 256) {
        int bb = i / HH, h = i % HH;
        rsh[bb][h] = g_h[bb * 320 + HH * (hop + 1) + h];
    }
    __syncthreads();
    int w = tid >> 5, lane = tid & 31;
    int t = blockIdx.x * 8 + w;
    const float* mp = Mp + (size_t)t * HH;
    float p = 0.f;
    #pragma unroll
    for (int h = 0; h < HH; h++) p += mp[h] * rsh[lane][h];
    size_t off = (size_t)t * BB + lane;
    float ysum = 0.f;
    #pragma unroll
    for (int k = 0; k < KSPLIT; k++) ysum += g_y[k][off];
    ztile[lane][w] = ysum * p * cz;
    __syncthreads();
    int b = tid >> 3, j = tid & 7;
    uint16_t pk; CVT_E5M2X2(pk, 0.f, ztile[b][j]);
    g_zb[(size_t)b * TT_ + blockIdx.x * 8 + j] = (uint8_t)(pk & 0xff);
}

// ---------------- final ----------------
__global__ void final_kernel(float* __restrict__ out, float f0, float f1, float f2) {
    int b = blockIdx.y;
    int n = blockIdx.x * 256 + threadIdx.x;
    float l0 = g_att[b * 3 + 0], l1 = g_att[b * 3 + 1], l2 = g_att[b * 3 + 2];
    float m = fmaxf(l0, fmaxf(l1, l2));
    float e0 = expf(l0 - m), e1 = expf(l1 - m), e2 = expf(l2 - m);
    float inv = 1.f / (e0 + e1 + e2);
    size_t off = (size_t)b * NEE + n;
    float x0 = 0.f, x1 = 0.f, x2 = 0.f;
    #pragma unroll
    for (int k = 0; k < KSPLIT; k++) {
        x0 += g_xp[0][k][off];
        x1 += g_xp[1][k][off];
        x2 += g_xp[2][k][off];
    }
    float v = x0 * f0 * e0 + x1 * f1 * e1 + x2 * f2 * e2;
    out[off] = 1.f / (1.f + expf(-v * inv));
}

// ---------------- launch ----------------
extern "C" void kernel_launch(void* const* d_in, const int* in_sizes, int n_in,
                              void* d_out, int out_size) {
    const float* span_embs = (const float*)d_in[0];
    const float* attention = (const float*)d_in[1];
    const float* qn_emb    = (const float*)d_in[2];
    const int*   trip_ids  = (const int*)  d_in[3];
    const int*   offsets   = (const int*)  d_in[4];
    const int*   qid_inds  = (const int*)  d_in[5];
    const float* emb_table = (const float*)d_in[6];
    const float* span_w    = (const float*)d_in[7];
    const float* span_b    = (const float*)d_in[8];
    const float* red_w     = (const float*)d_in[9];
    const float* red_b     = (const float*)d_in[10];
    const float* Ms        = (const float*)d_in[11];
    const float* Mo        = (const float*)d_in[12];
    const float* Mp        = (const float*)d_in[13];
    const float* inf_w[3]  = {(const float*)d_in[14], (const float*)d_in[16], (const float*)d_in[18]};
    const float* inf_b[3]  = {(const float*)d_in[15], (const float*)d_in[17], (const float*)d_in[19]};
    const float* att_w[3]  = {(const float*)d_in[20], (const float*)d_in[22], (const float*)d_in[24]};
    const float* att_b[3]  = {(const float*)d_in[21], (const float*)d_in[23], (const float*)d_in[25]};
    float* out = (float*)d_out;

    cudaFuncSetAttribute(fp8_gemm_kernel<false>,
                         cudaFuncAttributeMaxDynamicSharedMemorySize, GEMM_SMEM);
    cudaFuncSetAttribute(fp8_gemm_kernel<true>,
                         cudaFuncAttributeMaxDynamicSharedMemorySize, GEMM_SMEM);

    float *py, *pxp;
    cudaGetSymbolAddress((void**)&py,  g_y);
    cudaGetSymbolAddress((void**)&pxp, g_xp);
    uint8_t *pMsb, *pMoT, *pxb, *pzb;
    cudaGetSymbolAddress((void**)&pMsb, g_Msb);
    cudaGetSymbolAddress((void**)&pMoT, g_MoTb);
    cudaGetSymbolAddress((void**)&pxb,  g_xb);
    cudaGetSymbolAddress((void**)&pzb,  g_zb);

    const size_t YS = (size_t)TT_ * BB;
    const size_t XS = (size_t)BB * NEE;

    // scale schedule (powers of 2):  SX = {2^8, 2^26, 2^33};  SZ = {2^18, 2^24, 2^30}
    const float SX0 = 256.f;
    const float CZ[3] = { 8.f, 1.f / 512.f, 1.f / 1024.f };        // SZ/(128*SX)
    const float CB[3] = { 0.f, 2.f, 4.f };                          // SX/(128*SZ_prev)
    const float FX[3] = { 1.f / 33554432.f,                         // 1/(128*2^18) = 2^-25
                          1.f / 2147483648.f,                       // 2^-31
                          1.f / 137438953472.f };                   // 2^-37

    // slot #4 = fp8 GEMM1 (profiler captures launch #4)
    convMs_kernel<<<32768, 256>>>(Ms);                              // also zeroes g_sum1
    emb_dot_kernel<<<BB * 16, 256>>>(emb_table, trip_ids, attention, offsets, span_embs);
    cand_softmax_kernel<<<BB, 256>>>(span_embs, span_w, span_b, qid_inds, SX0);
    fp8_gemm_kernel<false><<<dim3(64, KSPLIT), 256, GEMM_SMEM>>>(pMsb, pxb, py, YS);
    convT_kernel<<<dim3(TT_ / 64, NEE / 32), dim3(32, 32)>>>(Mo);
    q_kernel<<<BB, 256>>>(qn_emb, red_w, red_b);

    for (int hop = 0; hop < HOPS; hop++) {
        r_kernel<<<BB, 128>>>(inf_w[hop], inf_b[hop], att_w[hop], att_b[hop], hop);
        if (hop > 0) {
            combine_xb_kernel<<<256, 256>>>(pxp + (size_t)(hop - 1) * KSPLIT * XS, CB[hop]);
            fp8_gemm_kernel<false><<<dim3(64, KSPLIT), 256, GEMM_SMEM>>>(pMsb, pxb, py, YS);
        }
        z_kernel<<<TT_ / 8, 256>>>(Mp, hop, CZ[hop]);
        fp8_gemm_kernel<true><<<dim3(64, KSPLIT), 256, GEMM_SMEM>>>(
            pMoT, pzb, pxp + (size_t)hop * KSPLIT * XS, XS);
    }
    final_kernel<<<dim3(NEE / 256, BB), 256>>>(out, FX[0], FX[1], FX[2]);
}

// round 11
// speedup vs baseline: 1.2208x; 1.0701x over previous
#include <cuda_runtime.h>
#include <cuda_bf16.h>
#include <cstdint>

// ---------------- model constants ----------------
#define BB   32
#define SS   8
#define DD   768
#define NEE  8192
#define TT_  8192
#define HH   80
#define LL   2048
#define SCC  256
#define HOPS 3
#define KSPLIT 8

// ---------------- PTX helpers ----------------
__device__ __forceinline__ uint32_t smem_to_u32(const void* smem_ptr) {
    uint32_t addr;
    asm("{ .reg .u64 tmp; cvta.to.shared.u64 tmp, %1; cvt.u32.u64 %0, tmp; }"
        : "=r"(addr) : "l"(smem_ptr));
    return addr;
}
#define CP_ASYNC16(dst_u32, src_ptr) \
    asm volatile("cp.async.cg.shared.global [%0], [%1], 16;" :: "r"(dst_u32), "l"(src_ptr))
#define CP_COMMIT() asm volatile("cp.async.commit_group;" ::: "memory")
#define CP_WAIT(n)  asm volatile("cp.async.wait_group %0;" :: "n"(n) : "memory")
#define LDMATRIX_X4(r0, r1, r2, r3, addr) \
    asm volatile("ldmatrix.sync.aligned.m8n8.x4.shared.b16 {%0,%1,%2,%3}, [%4];" \
        : "=r"(r0), "=r"(r1), "=r"(r2), "=r"(r3) : "r"(addr))
#define MMA_FP8(c, a0, a1, a2, a3, b0, b1) \
    asm volatile("mma.sync.aligned.m16n8k32.row.col.f32.e4m3.e5m2.f32 " \
        "{%0,%1,%2,%3}, {%4,%5,%6,%7}, {%8,%9}, {%0,%1,%2,%3};" \
        : "+f"((c)[0]), "+f"((c)[1]), "+f"((c)[2]), "+f"((c)[3]) \
        : "r"(a0), "r"(a1), "r"(a2), "r"(a3), "r"(b0), "r"(b1))
#define CVT_E4M3X2(r, hi, lo) \
    asm("cvt.rn.satfinite.e4m3x2.f32 %0, %1, %2;" : "=h"(r) : "f"(hi), "f"(lo))
#define CVT_E5M2X2(r, hi, lo) \
    asm("cvt.rn.satfinite.e5m2x2.f32 %0, %1, %2;" : "=h"(r) : "f"(hi), "f"(lo))

#define SCALE_M 128.0f

// ---------------- scratch (device globals) ----------------
__device__ float g_sum1[BB * SCC];
__device__ __align__(16) uint8_t g_xb[BB * NEE];
__device__ float g_y[KSPLIT][TT_ * BB];
__device__ __align__(16) uint8_t g_zb[BB * TT_];
__device__ float g_xp[HOPS][KSPLIT][BB * NEE];
__device__ float g_h[BB * 320];
__device__ float g_att[BB * 3];
__device__ __align__(16) uint8_t g_Msb[(size_t)TT_ * NEE];
__device__ __align__(16) uint8_t g_MoTb[(size_t)NEE * TT_];

// ---------------- Ms fp32 -> e4m3 x128 (+ zero g_sum1 in blocks 0..31) ----------------
__global__ void convMs_kernel(const float* __restrict__ Ms) {
    if (blockIdx.x < 32) g_sum1[blockIdx.x * 256 + threadIdx.x] = 0.f;
    size_t i = (size_t)blockIdx.x * 256 + threadIdx.x;
    float4 v0 = ((const float4*)Ms)[2 * i], v1 = ((const float4*)Ms)[2 * i + 1];
    uint16_t u0, u1, u2, u3;
    CVT_E4M3X2(u0, v0.y * SCALE_M, v0.x * SCALE_M);
    CVT_E4M3X2(u1, v0.w * SCALE_M, v0.z * SCALE_M);
    CVT_E4M3X2(u2, v1.y * SCALE_M, v1.x * SCALE_M);
    CVT_E4M3X2(u3, v1.w * SCALE_M, v1.z * SCALE_M);
    uint2 o;
    o.x = (uint32_t)u0 | ((uint32_t)u1 << 16);
    o.y = (uint32_t)u2 | ((uint32_t)u3 << 16);
    ((uint2*)g_Msb)[i] = o;
}

// ---------------- transpose + convert Mo -> MoT e4m3 x128 [n][t]  (v2: vectorized) ----------------
// tile: 128 t-rows x 32 n-cols; block (32,32)
__global__ void convT_kernel(const float* __restrict__ Mo) {
    __shared__ float sh[128][33];
    int t0 = blockIdx.x * 128, n0 = blockIdx.y * 32;
    int tx = threadIdx.x, ty = threadIdx.y;
    #pragma unroll
    for (int j = 0; j < 4; j++)
        sh[ty + 32 * j][tx] = Mo[(size_t)(t0 + ty + 32 * j) * NEE + n0 + tx];
    __syncthreads();
    // thread (tx,ty): n = n0+ty, t = t0 + 4*tx .. t0+4*tx+3  -> one uint32 store
    float a = sh[4 * tx + 0][ty] * SCALE_M;
    float b = sh[4 * tx + 1][ty] * SCALE_M;
    float c = sh[4 * tx + 2][ty] * SCALE_M;
    float d = sh[4 * tx + 3][ty] * SCALE_M;
    uint16_t p0, p1;
    CVT_E4M3X2(p0, b, a);
    CVT_E4M3X2(p1, d, c);
    ((uint32_t*)g_MoTb)[((size_t)(n0 + ty) * TT_ + t0) / 4 + tx] =
        (uint32_t)p0 | ((uint32_t)p1 << 16);
}

// ---------------- EmbeddingBag + span dot (v2: warp-per-element) ----------------
__device__ __forceinline__ int segsearch(const int* o, int l) {
    int lo = 0, hi = SCC;
    #pragma unroll
    for (int s = 0; s < 8; s++) {
        int mid = (lo + hi) >> 1;
        if (o[mid] <= l) lo = mid + 1; else hi = mid;
    }
    return lo - 1;
}

__global__ void __launch_bounds__(256) emb_dot_kernel(
        const float* __restrict__ emb,
        const int* __restrict__ ids,
        const float* __restrict__ att,
        const int* __restrict__ offs,
        const float* __restrict__ span_embs) {
    int b = blockIdx.x >> 4, chunk = blockIdx.x & 15;
    int tid = threadIdx.x, w = tid >> 5, lane = tid & 31;

    __shared__ float span_s[SS * DD];
    __shared__ int   offs_s[SCC];
    __shared__ float sum1_s[SCC];

    const float4* sp  = (const float4*)(span_embs + (size_t)b * SS * DD);
    float4*       sps = (float4*)span_s;
    #pragma unroll
    for (int i = 0; i < (SS * DD / 4) / 256; i++) sps[tid + i * 256] = sp[tid + i * 256];
    offs_s[tid] = offs[b * SCC + tid];
    sum1_s[tid] = 0.f;
    __syncthreads();

    const int bL   = b * LL;
    const int base = chunk * 128 + w * 16;

    #pragma unroll
    for (int i = 0; i < 16; i += 2) {
        int la = base + i, lb = base + i + 1;
        int   ida = ids[bL + la], idb = ids[bL + lb];
        float wa  = att[bL + la], wb  = att[bL + lb];
        int sega = segsearch(offs_s, la);
        int segb = segsearch(offs_s, lb);
        const float4* ra = (const float4*)(emb + (size_t)ida * DD);
        const float4* rb = (const float4*)(emb + (size_t)idb * DD);
        const float4* sa = (const float4*)(span_s + (sega & 7) * DD);
        const float4* sb = (const float4*)(span_s + (segb & 7) * DD);
        float da = 0.f, db = 0.f;
        #pragma unroll
        for (int j = 0; j < 6; j++) {
            float4 va = ra[lane + 32 * j];
            float4 xa = sa[lane + 32 * j];
            da += va.x * xa.x + va.y * xa.y + va.z * xa.z + va.w * xa.w;
            float4 vb = rb[lane + 32 * j];
            float4 xb = sb[lane + 32 * j];
            db += vb.x * xb.x + vb.y * xb.y + vb.z * xb.z + vb.w * xb.w;
        }
        #pragma unroll
        for (int o = 16; o; o >>= 1) {
            da += __shfl_xor_sync(0xffffffffu, da, o);
            db += __shfl_xor_sync(0xffffffffu, db, o);
        }
        if (lane == 0) {
            atomicAdd(&sum1_s[sega], wa * da);
            atomicAdd(&sum1_s[segb], wb * db);
        }
    }
    __syncthreads();
    atomicAdd(&g_sum1[b * SCC + tid], sum1_s[tid]);
}

// ---------------- fused: softmax chain -> cand -> scatter -> NE softmax -> e5m2 ----------------
__global__ void cand_softmax_kernel(const float* __restrict__ span_embs,
                                    const float* __restrict__ span_w,
                                    const float* __restrict__ span_b,
                                    const int* __restrict__ qid_inds,
                                    float sx0) {
    int b = blockIdx.x, tid = threadIdx.x;
    __shared__ float ent[NEE];
    __shared__ float sh_sum1[256];
    __shared__ float sh_score[8];
    __shared__ float red[8];
    __shared__ float bc;

    #pragma unroll
    for (int i = 0; i < NEE / 256; i++) ent[tid + i * 256] = 0.f;

    int w = tid >> 5, lane = tid & 31;
    {
        const float* se = span_embs + ((size_t)b * SS + w) * DD;
        float d = 0.f;
        for (int i = lane; i < DD; i += 32) d += se[i] * span_w[i];
        #pragma unroll
        for (int o = 16; o; o >>= 1) d += __shfl_xor_sync(0xffffffffu, d, o);
        if (lane == 0) sh_score[w] = d + span_b[0];
    }
    sh_sum1[tid] = g_sum1[b * SCC + tid];
    __syncthreads();

    int c = tid & 31, s = tid >> 5;
    float m = -1e30f;
    #pragma unroll
    for (int s2 = 0; s2 < 8; s2++) m = fmaxf(m, sh_sum1[s2 * 32 + c]);
    float den = 0.f;
    #pragma unroll
    for (int s2 = 0; s2 < 8; s2++) den += expf(sh_sum1[s2 * 32 + c] - m);
    float sm1 = expf(sh_sum1[tid] - m) / den;
    float tv  = sh_score[s] * sm1;

    float bm = tv;
    #pragma unroll
    for (int o = 16; o; o >>= 1) bm = fmaxf(bm, __shfl_xor_sync(0xffffffffu, bm, o));
    if (lane == 0) red[w] = bm;
    __syncthreads();
    if (tid == 0) { float x = red[0]; for (int j = 1; j < 8; j++) x = fmaxf(x, red[j]); bc = x; }
    __syncthreads();
    bm = bc;
    float e = expf(tv - bm);
    float sm = e;
    #pragma unroll
    for (int o = 16; o; o >>= 1) sm += __shfl_xor_sync(0xffffffffu, sm, o);
    __syncthreads();
    if (lane == 0) red[w] = sm;
    __syncthreads();
    if (tid == 0) { float x = 0.f; for (int j = 0; j < 8; j++) x += red[j]; bc = x; }
    __syncthreads();
    float cand = e / bc;

    int qid = qid_inds[b * SCC + tid];
    if (qid < NEE) atomicAdd(&ent[qid], cand);
    __syncthreads();

    float v[NEE / 256];
    m = -1e30f;
    #pragma unroll
    for (int i = 0; i < NEE / 256; i++) { v[i] = ent[tid + i * 256]; m = fmaxf(m, v[i]); }
    #pragma unroll
    for (int o = 16; o; o >>= 1) m = fmaxf(m, __shfl_xor_sync(0xffffffffu, m, o));
    if (lane == 0) red[w] = m;
    __syncthreads();
    if (tid == 0) { float x = red[0]; for (int j = 1; j < 8; j++) x = fmaxf(x, red[j]); bc = x; }
    __syncthreads();
    m = bc;
    float ssum = 0.f;
    #pragma unroll
    for (int i = 0; i < NEE / 256; i++) { v[i] = expf(v[i] - m); ssum += v[i]; }
    #pragma unroll
    for (int o = 16; o; o >>= 1) ssum += __shfl_xor_sync(0xffffffffu, ssum, o);
    __syncthreads();
    if (lane == 0) red[w] = ssum;
    __syncthreads();
    if (tid == 0) { float x = 0.f; for (int j = 0; j < 8; j++) x += red[j]; bc = x; }
    __syncthreads();
    float inv = sx0 / bc;
    uint8_t* orow = g_xb + (size_t)b * NEE;
    #pragma unroll
    for (int i = 0; i < NEE / 256; i++) {
        uint16_t pk; CVT_E5M2X2(pk, 0.f, v[i] * inv);
        orow[tid + i * 256] = (uint8_t)(pk & 0xff);
    }
}

// ---------------- combine KSPLIT split x partials -> e5m2 g_xb ----------------
__global__ void combine_xb_kernel(const float* __restrict__ p0, float cb) {
    size_t i = (size_t)blockIdx.x * 256 + threadIdx.x;
    const size_t XS = (size_t)BB * NEE;
    float4 v = ((const float4*)p0)[i];
    #pragma unroll
    for (int k = 1; k < KSPLIT; k++) {
        float4 w2 = ((const float4*)(p0 + k * XS))[i];
        v.x += w2.x; v.y += w2.y; v.z += w2.z; v.w += w2.w;
    }
    uint16_t u0, u1;
    CVT_E5M2X2(u0, v.y * cb, v.x * cb);
    CVT_E5M2X2(u1, v.w * cb, v.z * cb);
    ((uint32_t*)g_xb)[i] = (uint32_t)u0 | ((uint32_t)u1 << 16);
}

// ---------------- q = qn_emb @ red_w.T + red_b ----------------
__global__ void q_kernel(const float* __restrict__ qn,
                         const float* __restrict__ rw,
                         const float* __restrict__ rb) {
    int b = blockIdx.x;
    int w = threadIdx.x >> 5, lane = threadIdx.x & 31;
    const float* q = qn + (size_t)b * DD;
    for (int h = w; h < HH; h += 8) {
        const float* r = rw + (size_t)h * DD;
        float d = 0.f;
        for (int i = lane; i < DD; i += 32) d += q[i] * r[i];
        #pragma unroll
        for (int o = 16; o; o >>= 1) d += __shfl_xor_sync(0xffffffffu, d, o);
        if (lane == 0) g_h[b * 320 + h] = d + rb[h];
    }
}

// ---------------- per-hop r = softmax(h@W.T+b), att logit ----------------
__global__ void r_kernel(const float* __restrict__ W, const float* __restrict__ bias,
                         const float* __restrict__ aw, const float* __restrict__ ab, int hop) {
    int b = blockIdx.x, tid = threadIdx.x;
    int Wd = HH * (hop + 1);
    __shared__ float sh_h[240];
    __shared__ float sh_v[80];
    for (int i = tid; i < Wd; i += 128) sh_h[i] = g_h[b * 320 + i];
    __syncthreads();
    if (tid < 80) {
        float a = bias[tid];
        const float* row = W + (size_t)tid * Wd;
        for (int i = 0; i < Wd; i++) a += sh_h[i] * row[i];
        sh_v[tid] = a;
    } else if (tid == 80) {
        float a = ab[0];
        for (int i = 0; i < Wd; i++) a += sh_h[i] * aw[i];
        g_att[b * 3 + hop] = a;
    }
    __syncthreads();
    float m = -1e30f;
    for (int i = 0; i < 80; i++) m = fmaxf(m, sh_v[i]);
    float s = 0.f;
    for (int i = 0; i < 80; i++) s += expf(sh_v[i] - m);
    if (tid < 80) g_h[b * 320 + Wd + tid] = expf(sh_v[tid] - m) / s;
}

// =====================================================================
// FP8 MMA GEMM: split-K x8 (1024 K each), grid 512 -> ~3.5 CTAs/SM
// =====================================================================
#define KCHUNK 128
#define NIT    8    // 1024 / 128
#define SA_STAGE 16384
#define SB_STAGE 4096
#define GEMM_SMEM (4 * (SA_STAGE + SB_STAGE))

template<bool TRANS_OUT>
__global__ void __launch_bounds__(256) fp8_gemm_kernel(
    const uint8_t* __restrict__ A,
    const uint8_t* __restrict__ Bb,
    float* __restrict__ OutBase, size_t out_split_stride) {

    extern __shared__ uint8_t smem[];
    const uint32_t sAb = smem_to_u32(smem);
    const uint32_t sBb = sAb + 4 * SA_STAGE;

    const int tid  = threadIdx.x;
    const int wid  = tid >> 5;
    const int lane = tid & 31;
    const int mbase  = blockIdx.x * 128;
    const int kstart = blockIdx.y * (KCHUNK * NIT);
    float* Out = OutBase + blockIdx.y * out_split_stride;

    const uint8_t* Ab = A + (size_t)mbase * 8192 + kstart;
    const uint8_t* Bx = Bb + kstart;

    const int arow = tid >> 3;
    const int ac   = tid & 7;
    auto prefetch = [&](int it) {
        const int stage = it & 3;
        const uint32_t sa = sAb + stage * SA_STAGE;
        const uint32_t sb = sBb + stage * SB_STAGE;
        const uint8_t* ga = Ab + it * KCHUNK;
        #pragma unroll
        for (int j = 0; j < 4; j++) {
            int row = arow + j * 32;
            uint32_t dst = sa + row * 128 + ((ac ^ (row & 7)) << 4);
            CP_ASYNC16(dst, ga + (size_t)row * 8192 + ac * 16);
        }
        uint32_t dstb = sb + arow * 128 + ((ac ^ (arow & 7)) << 4);
        CP_ASYNC16(dstb, Bx + (size_t)arow * 8192 + it * KCHUNK + ac * 16);
    };

    prefetch(0); CP_COMMIT();
    prefetch(1); CP_COMMIT();
    prefetch(2); CP_COMMIT();

    float acc[4][4];
    #pragma unroll
    for (int j = 0; j < 4; j++)
        #pragma unroll
        for (int i = 0; i < 4; i++) acc[j][i] = 0.f;

    const int a_quad = lane >> 3;
    const int a_rloc = wid * 16 + (lane & 7) + (a_quad & 1) * 8;
    const int a_cke  = a_quad >> 1;
    const int b_n    = ((lane >> 4) * 8) + (lane & 7);
    const int b_cke  = (lane >> 3) & 1;

    for (int it = 0; it < NIT; it++) {
        if (it + 2 < NIT) { CP_WAIT(2); }
        else if (it + 1 < NIT) { CP_WAIT(1); }
        else { CP_WAIT(0); }
        __syncthreads();
        if (it + 3 < NIT) { prefetch(it + 3); CP_COMMIT(); }

        const int stage = it & 3;
        const uint32_t sa = sAb + stage * SA_STAGE;
        const uint32_t sb = sBb + stage * SB_STAGE;

        #pragma unroll
        for (int s = 0; s < 4; s++) {
            uint32_t a0, a1, a2, a3;
            {
                int c = s * 2 + a_cke;
                uint32_t addr = sa + a_rloc * 128 + ((c ^ (a_rloc & 7)) << 4);
                LDMATRIX_X4(a0, a1, a2, a3, addr);
            }
            uint32_t bL[4], bH[4];
            {
                int c = s * 2 + b_cke;
                uint32_t addr0 = sb + b_n * 128 + ((c ^ (b_n & 7)) << 4);
                LDMATRIX_X4(bL[0], bL[1], bL[2], bL[3], addr0);
                int n1 = 16 + b_n;
                uint32_t addr1 = sb + n1 * 128 + ((c ^ (n1 & 7)) << 4);
                LDMATRIX_X4(bH[0], bH[1], bH[2], bH[3], addr1);
            }
            MMA_FP8(acc[0], a0, a1, a2, a3, bL[0], bL[1]);
            MMA_FP8(acc[1], a0, a1, a2, a3, bL[2], bL[3]);
            MMA_FP8(acc[2], a0, a1, a2, a3, bH[0], bH[1]);
            MMA_FP8(acc[3], a0, a1, a2, a3, bH[2], bH[3]);
        }
    }

    if (!TRANS_OUT) {
        const int row0 = mbase + wid * 16 + (lane >> 2);
        #pragma unroll
        for (int j = 0; j < 4; j++) {
            int col = j * 8 + (lane & 3) * 2;
            *(float2*)(Out + (size_t)row0 * 32 + col) = make_float2(acc[j][0], acc[j][1]);
            *(float2*)(Out + (size_t)(row0 + 8) * 32 + col) = make_float2(acc[j][2], acc[j][3]);
        }
    } else {
        float* ep = (float*)smem;
        __syncthreads();
        const int mloc = wid * 16 + (lane >> 2);
        #pragma unroll
        for (int j = 0; j < 4; j++) {
            int col = j * 8 + (lane & 3) * 2;
            ep[col * 128 + mloc]           = acc[j][0];
            ep[(col + 1) * 128 + mloc]     = acc[j][1];
            ep[col * 128 + mloc + 8]       = acc[j][2];
            ep[(col + 1) * 128 + mloc + 8] = acc[j][3];
        }
        __syncthreads();
        #pragma unroll
        for (int i = 0; i < 16; i++) {
            int idx = tid + i * 256;
            int cc = idx >> 7, mm = idx & 127;
            Out[(size_t)cc * 8192 + mbase + mm] = ep[idx];
        }
    }
}

// ---------------- z: zb[b][t] = e5m2( (sum_ks y)[t][b] * dot(Mp[t], r[b]) * cz ) ----------------
__global__ void z_kernel(const float* __restrict__ Mp, int hop, float cz) {
    __shared__ float rsh[32][81];
    __shared__ float ztile[32][8];
    int tid = threadIdx.x;
    for (int i = tid; i < BB * HH; i += 256) {
        int bb = i / HH, h = i % HH;
        rsh[bb][h] = g_h[bb * 320 + HH * (hop + 1) + h];
    }
    __syncthreads();
    int w = tid >> 5, lane = tid & 31;
    int t = blockIdx.x * 8 + w;
    const float* mp = Mp + (size_t)t * HH;
    float p = 0.f;
    #pragma unroll
    for (int h = 0; h < HH; h++) p += mp[h] * rsh[lane][h];
    size_t off = (size_t)t * BB + lane;
    float ysum = 0.f;
    #pragma unroll
    for (int k = 0; k < KSPLIT; k++) ysum += g_y[k][off];
    ztile[lane][w] = ysum * p * cz;
    __syncthreads();
    int b = tid >> 3, j = tid & 7;
    uint16_t pk; CVT_E5M2X2(pk, 0.f, ztile[b][j]);
    g_zb[(size_t)b * TT_ + blockIdx.x * 8 + j] = (uint8_t)(pk & 0xff);
}

// ---------------- final ----------------
__global__ void final_kernel(float* __restrict__ out, float f0, float f1, float f2) {
    int b = blockIdx.y;
    int n = blockIdx.x * 256 + threadIdx.x;
    float l0 = g_att[b * 3 + 0], l1 = g_att[b * 3 + 1], l2 = g_att[b * 3 + 2];
    float m = fmaxf(l0, fmaxf(l1, l2));
    float e0 = expf(l0 - m), e1 = expf(l1 - m), e2 = expf(l2 - m);
    float inv = 1.f / (e0 + e1 + e2);
    size_t off = (size_t)b * NEE + n;
    float x0 = 0.f, x1 = 0.f, x2 = 0.f;
    #pragma unroll
    for (int k = 0; k < KSPLIT; k++) {
        x0 += g_xp[0][k][off];
        x1 += g_xp[1][k][off];
        x2 += g_xp[2][k][off];
    }
    float v = x0 * f0 * e0 + x1 * f1 * e1 + x2 * f2 * e2;
    out[off] = 1.f / (1.f + expf(-v * inv));
}

// ---------------- launch ----------------
extern "C" void kernel_launch(void* const* d_in, const int* in_sizes, int n_in,
                              void* d_out, int out_size) {
    const float* span_embs = (const float*)d_in[0];
    const float* attention = (const float*)d_in[1];
    const float* qn_emb    = (const float*)d_in[2];
    const int*   trip_ids  = (const int*)  d_in[3];
    const int*   offsets   = (const int*)  d_in[4];
    const int*   qid_inds  = (const int*)  d_in[5];
    const float* emb_table = (const float*)d_in[6];
    const float* span_w    = (const float*)d_in[7];
    const float* span_b    = (const float*)d_in[8];
    const float* red_w     = (const float*)d_in[9];
    const float* red_b     = (const float*)d_in[10];
    const float* Ms        = (const float*)d_in[11];
    const float* Mo        = (const float*)d_in[12];
    const float* Mp        = (const float*)d_in[13];
    const float* inf_w[3]  = {(const float*)d_in[14], (const float*)d_in[16], (const float*)d_in[18]};
    const float* inf_b[3]  = {(const float*)d_in[15], (const float*)d_in[17], (const float*)d_in[19]};
    const float* att_w[3]  = {(const float*)d_in[20], (const float*)d_in[22], (const float*)d_in[24]};
    const float* att_b[3]  = {(const float*)d_in[21], (const float*)d_in[23], (const float*)d_in[25]};
    float* out = (float*)d_out;

    cudaFuncSetAttribute(fp8_gemm_kernel<false>,
                         cudaFuncAttributeMaxDynamicSharedMemorySize, GEMM_SMEM);
    cudaFuncSetAttribute(fp8_gemm_kernel<true>,
                         cudaFuncAttributeMaxDynamicSharedMemorySize, GEMM_SMEM);

    float *py, *pxp;
    cudaGetSymbolAddress((void**)&py,  g_y);
    cudaGetSymbolAddress((void**)&pxp, g_xp);
    uint8_t *pMsb, *pMoT, *pxb, *pzb;
    cudaGetSymbolAddress((void**)&pMsb, g_Msb);
    cudaGetSymbolAddress((void**)&pMoT, g_MoTb);
    cudaGetSymbolAddress((void**)&pxb,  g_xb);
    cudaGetSymbolAddress((void**)&pzb,  g_zb);

    const size_t YS = (size_t)TT_ * BB;
    const size_t XS = (size_t)BB * NEE;

    // scale schedule (powers of 2):  SX = {2^8, 2^26, 2^33};  SZ = {2^18, 2^24, 2^30}
    const float SX0 = 256.f;
    const float CZ[3] = { 8.f, 1.f / 512.f, 1.f / 1024.f };
    const float CB[3] = { 0.f, 2.f, 4.f };
    const float FX[3] = { 1.f / 33554432.f, 1.f / 2147483648.f, 1.f / 137438953472.f };

    // slot #4 = convT v2 (profiler captures launch #4)
    convMs_kernel<<<32768, 256>>>(Ms);                              // also zeroes g_sum1
    emb_dot_kernel<<<BB * 16, 256>>>(emb_table, trip_ids, attention, offsets, span_embs);
    cand_softmax_kernel<<<BB, 256>>>(span_embs, span_w, span_b, qid_inds, SX0);
    convT_kernel<<<dim3(TT_ / 128, NEE / 32), dim3(32, 32)>>>(Mo);
    fp8_gemm_kernel<false><<<dim3(64, KSPLIT), 256, GEMM_SMEM>>>(pMsb, pxb, py, YS);
    q_kernel<<<BB, 256>>>(qn_emb, red_w, red_b);

    for (int hop = 0; hop < HOPS; hop++) {
        r_kernel<<<BB, 128>>>(inf_w[hop], inf_b[hop], att_w[hop], att_b[hop], hop);
        if (hop > 0) {
            combine_xb_kernel<<<256, 256>>>(pxp + (size_t)(hop - 1) * KSPLIT * XS, CB[hop]);
            fp8_gemm_kernel<false><<<dim3(64, KSPLIT), 256, GEMM_SMEM>>>(pMsb, pxb, py, YS);
        }
        z_kernel<<<TT_ / 8, 256>>>(Mp, hop, CZ[hop]);
        fp8_gemm_kernel<true><<<dim3(64, KSPLIT), 256, GEMM_SMEM>>>(
            pMoT, pzb, pxp + (size_t)hop * KSPLIT * XS, XS);
    }
    final_kernel<<<dim3(NEE / 256, BB), 256>>>(out, FX[0], FX[1], FX[2]);
}